// round 7
// baseline (speedup 1.0000x reference)
#include <cuda_runtime.h>
#include <math.h>

#define NB 16
#define SDIM 512

typedef unsigned long long ull;

__device__ __forceinline__ ull pack2(float a, float b) {
    ull r;
    asm("mov.b64 %0, {%1, %2};" : "=l"(r) : "f"(a), "f"(b));
    return r;
}
__device__ __forceinline__ void unpack2(ull v, float& a, float& b) {
    asm("mov.b64 {%0, %1}, %2;" : "=f"(a), "=f"(b) : "l"(v));
}
__device__ __forceinline__ void ffma2(ull& d, ull a, ull b) {
    asm("fma.rn.f32x2 %0, %1, %2, %0;" : "+l"(d) : "l"(a), "l"(b));
}

// ---------------- persistent scratch (no allocs allowed) ----------------
static __device__ float g_bufA[16777216];   // max: (16,64,128,128)
static __device__ float g_bufB[17040384];   // max: (16,64,129,129)

static __device__ float g_style0[NB * 256];
static __device__ float g_style1[NB * 128];
static __device__ float g_style2[NB * 128];
static __device__ float g_style3[NB * 64];
static __device__ float g_style4[NB * 64];
static __device__ float g_stylef[NB * 32];

static __device__ float g_demod0[NB * 128];
static __device__ float g_demod1[NB * 128];
static __device__ float g_demod2[NB * 64];
static __device__ float g_demod3[NB * 64];
static __device__ float g_demod4[NB * 32];

static __device__ float g_wsq0[128 * 256];
static __device__ float g_wsq1[128 * 128];
static __device__ float g_wsq2[64 * 128];
static __device__ float g_wsq3[64 * 64];
static __device__ float g_wsq4[32 * 64];

__device__ __forceinline__ float* style_ptr(int id) {
    switch (id) {
        case 0: return g_style0;
        case 1: return g_style1;
        case 2: return g_style2;
        case 3: return g_style3;
        case 4: return g_style4;
        default: return g_stylef;
    }
}
__device__ __forceinline__ float* demod_ptr(int id) {
    switch (id) {
        case 0: return g_demod0;
        case 1: return g_demod1;
        case 2: return g_demod2;
        case 3: return g_demod3;
        default: return g_demod4;
    }
}
__device__ __forceinline__ float* wsq_ptr(int id) {
    switch (id) {
        case 0: return g_wsq0;
        case 1: return g_wsq1;
        case 2: return g_wsq2;
        case 3: return g_wsq3;
        default: return g_wsq4;
    }
}

struct P6 { const float* a[6]; };
struct P5 { const float* a[5]; };

// ---------------- fused style kernel: all 6 layers ----------------
__global__ void style_all_kernel(const float* __restrict__ z, P6 mw, P6 mb) {
    int gw = blockIdx.x * 8 + (threadIdx.x >> 5);
    int lane = threadIdx.x & 31;
    if (gw >= NB * 672) return;
    int b = gw / 672;
    int c = gw - b * 672;
    int L, ci, Ci;
    if (c < 256)      { L = 0; ci = c;       Ci = 256; }
    else if (c < 384) { L = 1; ci = c - 256; Ci = 128; }
    else if (c < 512) { L = 2; ci = c - 384; Ci = 128; }
    else if (c < 576) { L = 3; ci = c - 512; Ci = 64; }
    else if (c < 640) { L = 4; ci = c - 576; Ci = 64; }
    else              { L = 5; ci = c - 640; Ci = 32; }
    const float* zr = z + b * SDIM;
    const float* mr = mw.a[L] + (size_t)ci * SDIM;
    float s = 0.f;
#pragma unroll 4
    for (int k = lane; k < SDIM; k += 32) s += zr[k] * mr[k];
#pragma unroll
    for (int o = 16; o; o >>= 1) s += __shfl_xor_sync(0xffffffffu, s, o);
    if (lane == 0)
        style_ptr(L)[b * Ci + ci] = s * 0.04419417382415922f + mb.a[L][ci];
}

// ---------------- fused wsq kernel: all 5 conv layers ----------------
__global__ void wsq_all_kernel(P5 w) {
    int i = blockIdx.x * 256 + threadIdx.x;  // < 63488 exactly
    int L, off, Ci;
    if (i < 32768)      { L = 0; off = i;         Ci = 256; }
    else if (i < 49152) { L = 1; off = i - 32768; Ci = 128; }
    else if (i < 57344) { L = 2; off = i - 49152; Ci = 128; }
    else if (i < 61440) { L = 3; off = i - 57344; Ci = 64; }
    else                { L = 4; off = i - 61440; Ci = 64; }
    const float* p = w.a[L] + (size_t)off * 9;
    float s = 0.f;
#pragma unroll
    for (int t = 0; t < 9; t++) s += p[t] * p[t];
    wsq_ptr(L)[off] = s * (1.0f / (float)(Ci * 9));
}

// ---------------- fused demod kernel: all 5 conv layers ----------------
__global__ void demod_all_kernel() {
    int gw = blockIdx.x * 8 + (threadIdx.x >> 5);
    int lane = threadIdx.x & 31;
    if (gw >= NB * 416) return;
    int b = gw / 416;
    int c = gw - b * 416;
    int L, co, Co, Ci;
    if (c < 128)      { L = 0; co = c;       Co = 128; Ci = 256; }
    else if (c < 256) { L = 1; co = c - 128; Co = 128; Ci = 128; }
    else if (c < 320) { L = 2; co = c - 256; Co = 64;  Ci = 128; }
    else if (c < 384) { L = 3; co = c - 320; Co = 64;  Ci = 64; }
    else              { L = 4; co = c - 384; Co = 32;  Ci = 64; }
    const float* st = style_ptr(L) + b * Ci;
    const float* wq = wsq_ptr(L) + (size_t)co * Ci;
    float s = 0.f;
    for (int ci = lane; ci < Ci; ci += 32) {
        float sv = st[ci];
        s += sv * sv * wq[ci];
    }
#pragma unroll
    for (int o = 16; o; o >>= 1) s += __shfl_xor_sync(0xffffffffu, s, o);
    if (lane == 0) demod_ptr(L)[b * Co + co] = rsqrtf(s + 1e-8f);
}

// ---------------- compose: bufA = (fg + (1-mask)*bg) * style0 ----------------
__global__ void compose_kernel(const float* __restrict__ fg,
                               const float* __restrict__ mask,
                               const float* __restrict__ bg) {
    int idx = blockIdx.x * blockDim.x + threadIdx.x;  // over 16*256*1024
    int p = idx & 1023;
    int c = (idx >> 10) & 255;
    int b = idx >> 18;
    float m = 1.0f - mask[b * 1024 + p];
    float v = fg[idx] + m * bg[idx];
    g_bufA[idx] = v * g_style0[b * 256 + c];
}

// ---------------- 3x3 conv: reg-prefetch double buffer, f32x2 packed --------
// Index math identical to the passing kernel; only buffering/order changed.
// epilogue: v = acc*demod + bias; v = leaky(v)*sqrt2*style_next
template <int CIN, int COUT, int H, int W, bool SRC_A>
__global__ __launch_bounds__(256) void conv3x3_kernel(const float* __restrict__ wraw,
                                                      const float* __restrict__ bias,
                                                      int demod_id, int style_id) {
    constexpr int CO_T = 32, CI_T = 8, TH = 8, TW = 32;
    constexpr int IN_LD = 36;   // float4-aligned rows
    constexpr int W_LD = 32;    // ull-aligned co pairs
    constexpr int TILES_X = W / TW;
    constexpr int IN_CNT = CI_T * (TH + 2) * 34;  // 2720 packed elements
    __shared__ __align__(16) float s_in[2][CI_T][TH + 2][IN_LD];
    __shared__ __align__(16) float s_w[2][CI_T][9][W_LD];

    const float* in = SRC_A ? g_bufA : g_bufB;
    float* out = SRC_A ? g_bufB : g_bufA;
    const float* demod = demod_ptr(demod_id);
    const float* styn = style_ptr(style_id);

    int tid = threadIdx.x;
    int tile = blockIdx.x;
    int tx0 = (tile % TILES_X) * TW;
    int ty0 = (tile / TILES_X) * TH;
    int co_base = blockIdx.y * CO_T;
    int b = blockIdx.z;

    int warp = tid >> 5;          // 0..7 -> co group of 4
    int lane = tid & 31;
    int r = lane >> 2;            // 0..7
    int c0 = (lane & 3) << 3;     // 0,8,16,24

    ull acc[2][8];
#pragma unroll
    for (int jp = 0; jp < 2; jp++)
#pragma unroll
        for (int p = 0; p < 8; p++) acc[jp][p] = 0ull;

    const float wscale = rsqrtf((float)(CIN * 9));
    const float* in_b = in + (size_t)b * CIN * H * W;

    float in_r[11], w_r[9];

    // load chunk cb into registers (index math verbatim from passing kernel)
    auto load_g = [&](int cb) {
#pragma unroll
        for (int k = 0; k < 11; k++) {
            int idx = tid + k * 256;
            float v = 0.f;
            if (idx < IN_CNT) {
                int ci = idx / ((TH + 2) * 34);
                int rem = idx % ((TH + 2) * 34);
                int iy = rem / 34, ix = rem % 34;
                int gy = ty0 + iy - 1, gx = tx0 + ix - 1;
                if (gy >= 0 && gy < H && gx >= 0 && gx < W)
                    v = in_b[(size_t)(cb + ci) * H * W + gy * W + gx];
            }
            in_r[k] = v;
        }
#pragma unroll
        for (int k = 0; k < 9; k++) {
            int idx = tid + k * 256;  // CO_T*CI_T*9 = 2304 = 9*256 exactly
            int co = idx / (CI_T * 9);
            int rem = idx % (CI_T * 9);
            int ci = rem / 9, tap = rem % 9;
            w_r[k] = wraw[((size_t)(co_base + co) * CIN + cb + ci) * 9 + tap];
        }
    };
    auto store_s = [&](int bsel) {
#pragma unroll
        for (int k = 0; k < 11; k++) {
            int idx = tid + k * 256;
            if (idx < IN_CNT) {
                int ci = idx / ((TH + 2) * 34);
                int rem = idx % ((TH + 2) * 34);
                int iy = rem / 34, ix = rem % 34;
                s_in[bsel][ci][iy][ix] = in_r[k];
            }
        }
#pragma unroll
        for (int k = 0; k < 9; k++) {
            int idx = tid + k * 256;
            int co = idx / (CI_T * 9);
            int rem = idx % (CI_T * 9);
            int ci = rem / 9, tap = rem % 9;
            s_w[bsel][ci][tap][co] = w_r[k] * wscale;
        }
    };

    load_g(0);
    store_s(0);
    __syncthreads();

    for (int cb = 0; cb < CIN; cb += CI_T) {
        int buf = (cb / CI_T) & 1;
        bool more = (cb + CI_T < CIN);
        if (more) load_g(cb + CI_T);  // LDGs issue; data lands during compute
#pragma unroll
        for (int ci = 0; ci < CI_T; ci++) {
#pragma unroll
            for (int ky = 0; ky < 3; ky++) {
                const float4* row4 =
                    reinterpret_cast<const float4*>(&s_in[buf][ci][r + ky][c0]);
                float4 q0 = row4[0];
                float4 q1 = row4[1];
                float4 q2 = row4[2];
                ull xd[10];
                xd[0] = pack2(q0.x, q0.x); xd[1] = pack2(q0.y, q0.y);
                xd[2] = pack2(q0.z, q0.z); xd[3] = pack2(q0.w, q0.w);
                xd[4] = pack2(q1.x, q1.x); xd[5] = pack2(q1.y, q1.y);
                xd[6] = pack2(q1.z, q1.z); xd[7] = pack2(q1.w, q1.w);
                xd[8] = pack2(q2.x, q2.x); xd[9] = pack2(q2.y, q2.y);
#pragma unroll
                for (int kx = 0; kx < 3; kx++) {
#pragma unroll
                    for (int jp = 0; jp < 2; jp++) {
                        ull w2 = *reinterpret_cast<const ull*>(
                            &s_w[buf][ci][ky * 3 + kx][warp * 4 + jp * 2]);
#pragma unroll
                        for (int p = 0; p < 8; p++) ffma2(acc[jp][p], w2, xd[kx + p]);
                    }
                }
            }
        }
        if (more) store_s(buf ^ 1);
        __syncthreads();
    }

    // epilogue
    int oy = ty0 + r;
    float* out_b = out + (size_t)b * COUT * H * W;
#pragma unroll
    for (int jp = 0; jp < 2; jp++) {
        float vlo[8], vhi[8];
#pragma unroll
        for (int p = 0; p < 8; p++) unpack2(acc[jp][p], vlo[p], vhi[p]);
#pragma unroll
        for (int h = 0; h < 2; h++) {
            int co = co_base + warp * 4 + jp * 2 + h;
            float dm = demod[b * COUT + co];
            float bi = bias[co];
            float sn = styn[b * COUT + co];
            float* op = out_b + (size_t)co * H * W + oy * W + tx0 + c0;
            const float* src = h ? vhi : vlo;
            float4 o0, o1;
            float vv[8];
#pragma unroll
            for (int p = 0; p < 8; p++) {
                float v = src[p] * dm + bi;
                vv[p] = (v > 0.f ? v : 0.2f * v) * 1.41421356237309515f * sn;
            }
            o0.x = vv[0]; o0.y = vv[1]; o0.z = vv[2]; o0.w = vv[3];
            o1.x = vv[4]; o1.y = vv[5]; o1.z = vv[6]; o1.w = vv[7];
            reinterpret_cast<float4*>(op)[0] = o0;
            reinterpret_cast<float4*>(op)[1] = o1;
        }
    }
}

// ---------------- transposed conv (UNCHANGED passing version) ---------------
template <int CIN, int COUT, int HIN, bool SRC_A>
__global__ __launch_bounds__(256) void tconv_kernel(const float* __restrict__ wraw,
                                                    int demod_id) {
    constexpr int HOUT = 2 * HIN + 1;
    constexpr int CO_T = 32, CI_T = 8, TH = 8, TW = 32;
    constexpr int IR = 6, ICW = 18, IC_LD = 19;
    constexpr int W_LD = 32;
    constexpr int TILES_X = (HOUT + TW - 1) / TW;
    __shared__ __align__(16) float s_in[CI_T][IR][IC_LD];
    __shared__ __align__(16) float s_w[CI_T][9][W_LD];

    const float* in = SRC_A ? g_bufA : g_bufB;
    float* out = SRC_A ? g_bufB : g_bufA;
    const float* demod = demod_ptr(demod_id);

    int tid = threadIdx.x;
    int tile = blockIdx.x;
    int tx0 = (tile % TILES_X) * TW;
    int ty0 = (tile / TILES_X) * TH;
    int co_base = blockIdx.y * CO_T;
    int b = blockIdx.z;

    int co_grp = tid >> 6;
    int lane = tid & 31;
    int wrp = tid >> 5;
    int r = 2 * ((lane >> 3) & 3) + (wrp & 1);
    int c0 = (lane & 7) << 2;
    int h = c0 >> 1;

    int iy_base = (ty0 >> 1) - 1;
    int jx_base = (tx0 >> 1) - 1;

    ull acc[4][4];
#pragma unroll
    for (int jp = 0; jp < 4; jp++)
#pragma unroll
        for (int p = 0; p < 4; p++) acc[jp][p] = 0ull;

    const float wscale = rsqrtf((float)(CIN * 9));
    const float* in_b = in + (size_t)b * CIN * HIN * HIN;

    for (int cb = 0; cb < CIN; cb += CI_T) {
        __syncthreads();
        for (int idx = tid; idx < CI_T * IR * ICW; idx += 256) {
            int ci = idx / (IR * ICW);
            int rem = idx % (IR * ICW);
            int iy = rem / ICW, ix = rem % ICW;
            int gy = iy_base + iy, gx = jx_base + ix;
            float v = 0.f;
            if (gy >= 0 && gy < HIN && gx >= 0 && gx < HIN)
                v = in_b[(size_t)(cb + ci) * HIN * HIN + gy * HIN + gx];
            s_in[ci][iy][ix] = v;
        }
        for (int idx = tid; idx < CO_T * CI_T * 9; idx += 256) {
            int co = idx / (CI_T * 9);
            int rem = idx % (CI_T * 9);
            int ci = rem / 9, tap = rem % 9;
            s_w[ci][tap][co] =
                wraw[((size_t)(co_base + co) * CIN + cb + ci) * 9 + tap] * wscale;
        }
        __syncthreads();
#pragma unroll
        for (int ci = 0; ci < CI_T; ci++) {
            int ky0 = r & 1;
            for (int ky = ky0; ky < 3; ky += 2) {
                int ir = ((r + ky - 2) >> 1) + 1;
                float x0v = s_in[ci][ir][h];
                float x1v = s_in[ci][ir][h + 1];
                float x2v = s_in[ci][ir][h + 2];
                ull xd0 = pack2(x0v, x0v);
                ull xd1 = pack2(x1v, x1v);
                ull xd2 = pack2(x2v, x2v);
                int wr = (2 - ky) * 3;
#pragma unroll
                for (int jp = 0; jp < 4; jp++) {
                    int co = co_grp * 8 + jp * 2;
                    ull w0 = *reinterpret_cast<const ull*>(&s_w[ci][wr + 0][co]);
                    ull w1 = *reinterpret_cast<const ull*>(&s_w[ci][wr + 1][co]);
                    ull w2 = *reinterpret_cast<const ull*>(&s_w[ci][wr + 2][co]);
                    ffma2(acc[jp][0], w2, xd0);
                    ffma2(acc[jp][0], w0, xd1);
                    ffma2(acc[jp][1], w1, xd1);
                    ffma2(acc[jp][2], w2, xd1);
                    ffma2(acc[jp][2], w0, xd2);
                    ffma2(acc[jp][3], w1, xd2);
                }
            }
        }
    }
    int oy = ty0 + r;
    if (oy >= HOUT) return;
    float* out_b = out + (size_t)b * COUT * HOUT * HOUT;
#pragma unroll
    for (int jp = 0; jp < 4; jp++) {
#pragma unroll
        for (int hh = 0; hh < 2; hh++) {
            int co = co_base + co_grp * 8 + jp * 2 + hh;
            float dm = demod[b * COUT + co];
#pragma unroll
            for (int p = 0; p < 4; p++) {
                float lo, hi;
                unpack2(acc[jp][p], lo, hi);
                float v = (hh ? hi : lo) * dm;
                int ox = tx0 + c0 + p;
                if (ox < HOUT)
                    out_b[(size_t)co * HOUT * HOUT + oy * HOUT + ox] = v;
            }
        }
    }
}

// ---------------- 4x4 blur (pad 1, HIN -> HIN-1) + bias + leaky*sqrt2*style_next
template <int C, int HIN, bool SRC_A>
__global__ __launch_bounds__(256) void blur_kernel(const float* __restrict__ bias,
                                                   int style_id) {
    constexpr int HOUT = HIN - 1;
    constexpr int TH = 16, TW = 32;
    constexpr int TILES_X = HOUT / TW;
    __shared__ float s[TH + 3][TW + 4];

    const float* in = SRC_A ? g_bufA : g_bufB;
    float* out = SRC_A ? g_bufB : g_bufA;

    int tile = blockIdx.x;
    int x0 = (tile % TILES_X) * TW;
    int y0 = (tile / TILES_X) * TH;
    int c = blockIdx.y, b = blockIdx.z;
    const float* ip = in + ((size_t)b * C + c) * HIN * HIN;

    for (int idx = threadIdx.x; idx < (TH + 3) * (TW + 3); idx += 256) {
        int iy = idx / (TW + 3), ix = idx % (TW + 3);
        int gy = y0 + iy - 1, gx = x0 + ix - 1;
        float v = 0.f;
        if (gy >= 0 && gy < HIN && gx >= 0 && gx < HIN) v = ip[gy * HIN + gx];
        s[iy][ix] = v;
    }
    __syncthreads();

    const float c4[4] = {0.25f, 0.75f, 0.75f, 0.25f};
    float bi = bias[c];
    float sn = style_ptr(style_id)[b * C + c];
    float* op = out + ((size_t)b * C + c) * HOUT * HOUT;
#pragma unroll
    for (int q = 0; q < 2; q++) {
        int px = threadIdx.x + q * 256;
        int ly = px >> 5, lx = px & 31;
        float a = 0.f;
#pragma unroll
        for (int ky = 0; ky < 4; ky++) {
            float rs = 0.f;
#pragma unroll
            for (int kx = 0; kx < 4; kx++) rs += c4[kx] * s[ly + ky][lx + kx];
            a += c4[ky] * rs;
        }
        a += bi;
        a = (a > 0.f ? a : 0.2f * a) * 1.41421356237309515f * sn;
        op[(y0 + ly) * HOUT + x0 + lx] = a;
    }
}

// ---------------- final 1x1 (32 -> 3 of 4 ch), no demod, + out_bias ---------
__global__ void final_kernel(const float* __restrict__ finw,
                             const float* __restrict__ outb,
                             float* __restrict__ out) {
    int idx = blockIdx.x * blockDim.x + threadIdx.x;  // over 16*16384
    int b = idx >> 14;
    int p = idx & 16383;
    const float* ib = g_bufB + (size_t)b * 32 * 16384 + p;
    float a0 = 0.f, a1 = 0.f, a2 = 0.f;
#pragma unroll
    for (int ci = 0; ci < 32; ci++) {
        float v = ib[(size_t)ci * 16384];
        a0 = fmaf(finw[ci], v, a0);
        a1 = fmaf(finw[32 + ci], v, a1);
        a2 = fmaf(finw[64 + ci], v, a2);
    }
    const float sc = rsqrtf(32.0f);
    out[(size_t)b * 3 * 16384 + p] = a0 * sc + outb[0];
    out[(size_t)b * 3 * 16384 + 16384 + p] = a1 * sc + outb[1];
    out[(size_t)b * 3 * 16384 + 2 * 16384 + p] = a2 * sc + outb[2];
}

// ------------------------------------------------------------------------
extern "C" void kernel_launch(void* const* d_in, const int* in_sizes, int n_in,
                              void* d_out, int out_size) {
    (void)in_sizes; (void)n_in; (void)out_size;
    const float* fg = (const float*)d_in[0];
    const float* mask = (const float*)d_in[1];
    const float* bg = (const float*)d_in[2];
    const float* z = (const float*)d_in[3];
    const float* l_w[5]  = {(const float*)d_in[4],  (const float*)d_in[8],
                            (const float*)d_in[12], (const float*)d_in[16],
                            (const float*)d_in[20]};
    const float* l_mw[5] = {(const float*)d_in[5],  (const float*)d_in[9],
                            (const float*)d_in[13], (const float*)d_in[17],
                            (const float*)d_in[21]};
    const float* l_mb[5] = {(const float*)d_in[6],  (const float*)d_in[10],
                            (const float*)d_in[14], (const float*)d_in[18],
                            (const float*)d_in[22]};
    const float* l_b[5]  = {(const float*)d_in[7],  (const float*)d_in[11],
                            (const float*)d_in[15], (const float*)d_in[19],
                            (const float*)d_in[23]};
    const float* finw = (const float*)d_in[24];
    const float* fin_mw = (const float*)d_in[25];
    const float* fin_mb = (const float*)d_in[26];
    const float* outb = (const float*)d_in[27];

    // fused setup: styles (6 layers), wsq (5), demod (5)
    P6 mw6, mb6;
    for (int l = 0; l < 5; l++) { mw6.a[l] = l_mw[l]; mb6.a[l] = l_mb[l]; }
    mw6.a[5] = fin_mw; mb6.a[5] = fin_mb;
    style_all_kernel<<<1344, 256>>>(z, mw6, mb6);
    P5 w5;
    for (int l = 0; l < 5; l++) w5.a[l] = l_w[l];
    wsq_all_kernel<<<248, 256>>>(w5);
    demod_all_kernel<<<832, 256>>>();

    // compose + modulate for layer 0 -> bufA
    compose_kernel<<<(NB * 256 * 1024) / 256, 256>>>(fg, mask, bg);

    // l0: 256->128 @32x32   (A -> B), epilogue styles for l1
    conv3x3_kernel<256, 128, 32, 32, true><<<dim3(4, 4, NB), 256>>>(l_w[0], l_b[0], 0, 1);
    // l1: tconv 128->128, 32 -> 65   (B -> A)
    tconv_kernel<128, 128, 32, false><<<dim3(27, 4, NB), 256>>>(l_w[1], 1);
    // blur 65 -> 64 + act + style2   (A -> B)
    blur_kernel<128, 65, true><<<dim3(8, 128, NB), 256>>>(l_b[1], 2);
    // l2: 128->64 @64x64   (B -> A), epilogue style3
    conv3x3_kernel<128, 64, 64, 64, false><<<dim3(16, 2, NB), 256>>>(l_w[2], l_b[2], 2, 3);
    // l3: tconv 64->64, 64 -> 129   (A -> B)
    tconv_kernel<64, 64, 64, true><<<dim3(85, 2, NB), 256>>>(l_w[3], 3);
    // blur 129 -> 128 + act + style4   (B -> A)
    blur_kernel<64, 129, false><<<dim3(32, 64, NB), 256>>>(l_b[3], 4);
    // l4: 64->32 @128x128   (A -> B), epilogue style_fin
    conv3x3_kernel<64, 32, 128, 128, true><<<dim3(64, 1, NB), 256>>>(l_w[4], l_b[4], 4, 5);
    // final 1x1 32->3 + out_bias   (B -> d_out)
    final_kernel<<<(NB * 16384) / 256, 256>>>(finw, outb, (float*)d_out);
}

// round 8
// speedup vs baseline: 1.0361x; 1.0361x over previous
#include <cuda_runtime.h>
#include <math.h>

#define NB 16
#define SDIM 512

typedef unsigned long long ull;

__device__ __forceinline__ ull pack2(float a, float b) {
    ull r;
    asm("mov.b64 %0, {%1, %2};" : "=l"(r) : "f"(a), "f"(b));
    return r;
}
__device__ __forceinline__ void unpack2(ull v, float& a, float& b) {
    asm("mov.b64 {%0, %1}, %2;" : "=f"(a), "=f"(b) : "l"(v));
}
__device__ __forceinline__ void ffma2(ull& d, ull a, ull b) {
    asm("fma.rn.f32x2 %0, %1, %2, %0;" : "+l"(d) : "l"(a), "l"(b));
}

// ---------------- persistent scratch (no allocs allowed) ----------------
static __device__ float g_bufA[16777216];   // max: (16,64,128,128)
static __device__ float g_bufB[17040384];   // max: (16,64,129,129)

static __device__ float g_style0[NB * 256];
static __device__ float g_style1[NB * 128];
static __device__ float g_style2[NB * 128];
static __device__ float g_style3[NB * 64];
static __device__ float g_style4[NB * 64];
static __device__ float g_stylef[NB * 32];

static __device__ float g_demod0[NB * 128];
static __device__ float g_demod1[NB * 128];
static __device__ float g_demod2[NB * 64];
static __device__ float g_demod3[NB * 64];
static __device__ float g_demod4[NB * 32];

__device__ __forceinline__ float* style_ptr(int id) {
    switch (id) {
        case 0: return g_style0;
        case 1: return g_style1;
        case 2: return g_style2;
        case 3: return g_style3;
        case 4: return g_style4;
        default: return g_stylef;
    }
}
__device__ __forceinline__ float* demod_ptr(int id) {
    switch (id) {
        case 0: return g_demod0;
        case 1: return g_demod1;
        case 2: return g_demod2;
        case 3: return g_demod3;
        default: return g_demod4;
    }
}

struct P6 { const float* a[6]; };
struct P5 { const float* a[5]; };

// ---------------- fused style kernel: all 6 layers (proven R7) ----------------
__global__ void style_all_kernel(const float* __restrict__ z, P6 mw, P6 mb) {
    int gw = blockIdx.x * 8 + (threadIdx.x >> 5);
    int lane = threadIdx.x & 31;
    if (gw >= NB * 672) return;
    int b = gw / 672;
    int c = gw - b * 672;
    int L, ci, Ci;
    if (c < 256)      { L = 0; ci = c;       Ci = 256; }
    else if (c < 384) { L = 1; ci = c - 256; Ci = 128; }
    else if (c < 512) { L = 2; ci = c - 384; Ci = 128; }
    else if (c < 576) { L = 3; ci = c - 512; Ci = 64; }
    else if (c < 640) { L = 4; ci = c - 576; Ci = 64; }
    else              { L = 5; ci = c - 640; Ci = 32; }
    const float* zr = z + b * SDIM;
    const float* mr = mw.a[L] + (size_t)ci * SDIM;
    float s = 0.f;
#pragma unroll 4
    for (int k = lane; k < SDIM; k += 32) s += zr[k] * mr[k];
#pragma unroll
    for (int o = 16; o; o >>= 1) s += __shfl_xor_sync(0xffffffffu, s, o);
    if (lane == 0)
        style_ptr(L)[b * Ci + ci] = s * 0.04419417382415922f + mb.a[L][ci];
}

// ---------------- fused demod kernel, wsq inline: all 5 conv layers ----------
// demod[b,co] = rsqrt( sum_ci style[b,ci]^2 * (sum_tap w[co,ci,tap]^2)/(Ci*9) + 1e-8 )
__global__ void demod_all_kernel(P5 w) {
    int gw = blockIdx.x * 8 + (threadIdx.x >> 5);
    int lane = threadIdx.x & 31;
    if (gw >= NB * 416) return;
    int b = gw / 416;
    int c = gw - b * 416;
    int L, co, Co, Ci;
    if (c < 128)      { L = 0; co = c;       Co = 128; Ci = 256; }
    else if (c < 256) { L = 1; co = c - 128; Co = 128; Ci = 128; }
    else if (c < 320) { L = 2; co = c - 256; Co = 64;  Ci = 128; }
    else if (c < 384) { L = 3; co = c - 320; Co = 64;  Ci = 64; }
    else              { L = 4; co = c - 384; Co = 32;  Ci = 64; }
    const float* st = style_ptr(L) + b * Ci;
    const float* wb = w.a[L] + (size_t)co * Ci * 9;
    float s = 0.f;
    for (int ci = lane; ci < Ci; ci += 32) {
        const float* p = wb + ci * 9;
        float wq = 0.f;
#pragma unroll
        for (int t = 0; t < 9; t++) wq += p[t] * p[t];
        float sv = st[ci];
        s += sv * sv * wq;
    }
#pragma unroll
    for (int o = 16; o; o >>= 1) s += __shfl_xor_sync(0xffffffffu, s, o);
    if (lane == 0)
        demod_ptr(L)[b * Co + co] = rsqrtf(s * (1.0f / (float)(Ci * 9)) + 1e-8f);
}

// ---------------- compose: bufA = (fg + (1-mask)*bg) * style0 ----------------
__global__ void compose_kernel(const float* __restrict__ fg,
                               const float* __restrict__ mask,
                               const float* __restrict__ bg) {
    int idx = blockIdx.x * blockDim.x + threadIdx.x;  // over 16*256*1024
    int p = idx & 1023;
    int c = (idx >> 10) & 255;
    int b = idx >> 18;
    float m = 1.0f - mask[b * 1024 + p];
    float v = fg[idx] + m * bg[idx];
    g_bufA[idx] = v * g_style0[b * 256 + c];
}

// ---------------- 3x3 conv, pad 1, f32x2-packed over co pairs ----------------
// (exact best-known 1724us body)
template <int CIN, int COUT, int H, int W, bool SRC_A>
__global__ __launch_bounds__(256) void conv3x3_kernel(const float* __restrict__ wraw,
                                                      const float* __restrict__ bias,
                                                      int demod_id, int style_id) {
    constexpr int CO_T = 32, CI_T = 8, TH = 8, TW = 32;
    constexpr int IN_LD = 36;
    constexpr int W_LD = 32;
    constexpr int TILES_X = W / TW;
    __shared__ __align__(16) float s_in[CI_T][TH + 2][IN_LD];
    __shared__ __align__(16) float s_w[CI_T][9][W_LD];

    const float* in = SRC_A ? g_bufA : g_bufB;
    float* out = SRC_A ? g_bufB : g_bufA;
    const float* demod = demod_ptr(demod_id);
    const float* styn = style_ptr(style_id);

    int tid = threadIdx.x;
    int tile = blockIdx.x;
    int tx0 = (tile % TILES_X) * TW;
    int ty0 = (tile / TILES_X) * TH;
    int co_base = blockIdx.y * CO_T;
    int b = blockIdx.z;

    int warp = tid >> 5;          // 0..7 -> co group of 4
    int lane = tid & 31;
    int r = lane >> 2;            // 0..7
    int c0 = (lane & 3) << 3;     // 0,8,16,24

    ull acc[2][8];
#pragma unroll
    for (int jp = 0; jp < 2; jp++)
#pragma unroll
        for (int p = 0; p < 8; p++) acc[jp][p] = 0ull;

    const float wscale = rsqrtf((float)(CIN * 9));
    const float* in_b = in + (size_t)b * CIN * H * W;

    for (int cb = 0; cb < CIN; cb += CI_T) {
        __syncthreads();
        // input tile (with halo), zero-padded at edges
        for (int idx = tid; idx < CI_T * (TH + 2) * 34; idx += 256) {
            int ci = idx / ((TH + 2) * 34);
            int rem = idx % ((TH + 2) * 34);
            int iy = rem / 34, ix = rem % 34;
            int gy = ty0 + iy - 1, gx = tx0 + ix - 1;
            float v = 0.f;
            if (gy >= 0 && gy < H && gx >= 0 && gx < W)
                v = in_b[(size_t)(cb + ci) * H * W + gy * W + gx];
            s_in[ci][iy][ix] = v;
        }
        // weights (pre-scaled)
        for (int idx = tid; idx < CO_T * CI_T * 9; idx += 256) {
            int co = idx / (CI_T * 9);
            int rem = idx % (CI_T * 9);
            int ci = rem / 9, tap = rem % 9;
            s_w[ci][tap][co] =
                wraw[((size_t)(co_base + co) * CIN + cb + ci) * 9 + tap] * wscale;
        }
        __syncthreads();
#pragma unroll
        for (int ci = 0; ci < CI_T; ci++) {
#pragma unroll
            for (int ky = 0; ky < 3; ky++) {
                const float4* row4 =
                    reinterpret_cast<const float4*>(&s_in[ci][r + ky][c0]);
                float4 q0 = row4[0];
                float4 q1 = row4[1];
                float4 q2 = row4[2];
                ull xd[10];
                xd[0] = pack2(q0.x, q0.x); xd[1] = pack2(q0.y, q0.y);
                xd[2] = pack2(q0.z, q0.z); xd[3] = pack2(q0.w, q0.w);
                xd[4] = pack2(q1.x, q1.x); xd[5] = pack2(q1.y, q1.y);
                xd[6] = pack2(q1.z, q1.z); xd[7] = pack2(q1.w, q1.w);
                xd[8] = pack2(q2.x, q2.x); xd[9] = pack2(q2.y, q2.y);
#pragma unroll
                for (int kx = 0; kx < 3; kx++) {
#pragma unroll
                    for (int jp = 0; jp < 2; jp++) {
                        ull w2 = *reinterpret_cast<const ull*>(
                            &s_w[ci][ky * 3 + kx][warp * 4 + jp * 2]);
#pragma unroll
                        for (int p = 0; p < 8; p++) ffma2(acc[jp][p], w2, xd[kx + p]);
                    }
                }
            }
        }
    }
    // epilogue
    int oy = ty0 + r;
    float* out_b = out + (size_t)b * COUT * H * W;
#pragma unroll
    for (int jp = 0; jp < 2; jp++) {
        float vlo[8], vhi[8];
#pragma unroll
        for (int p = 0; p < 8; p++) unpack2(acc[jp][p], vlo[p], vhi[p]);
#pragma unroll
        for (int h = 0; h < 2; h++) {
            int co = co_base + warp * 4 + jp * 2 + h;
            float dm = demod[b * COUT + co];
            float bi = bias[co];
            float sn = styn[b * COUT + co];
            float* op = out_b + (size_t)co * H * W + oy * W + tx0 + c0;
            const float* src = h ? vhi : vlo;
            float4 o0, o1;
            float vv[8];
#pragma unroll
            for (int p = 0; p < 8; p++) {
                float v = src[p] * dm + bi;
                vv[p] = (v > 0.f ? v : 0.2f * v) * 1.41421356237309515f * sn;
            }
            o0.x = vv[0]; o0.y = vv[1]; o0.z = vv[2]; o0.w = vv[3];
            o1.x = vv[4]; o1.y = vv[5]; o1.z = vv[6]; o1.w = vv[7];
            reinterpret_cast<float4*>(op)[0] = o0;
            reinterpret_cast<float4*>(op)[1] = o1;
        }
    }
}

// ---------------- transposed conv (exact best-known body) -------------------
template <int CIN, int COUT, int HIN, bool SRC_A>
__global__ __launch_bounds__(256) void tconv_kernel(const float* __restrict__ wraw,
                                                    int demod_id) {
    constexpr int HOUT = 2 * HIN + 1;
    constexpr int CO_T = 32, CI_T = 8, TH = 8, TW = 32;
    constexpr int IR = 6, ICW = 18, IC_LD = 19;
    constexpr int W_LD = 32;
    constexpr int TILES_X = (HOUT + TW - 1) / TW;
    __shared__ __align__(16) float s_in[CI_T][IR][IC_LD];
    __shared__ __align__(16) float s_w[CI_T][9][W_LD];

    const float* in = SRC_A ? g_bufA : g_bufB;
    float* out = SRC_A ? g_bufB : g_bufA;
    const float* demod = demod_ptr(demod_id);

    int tid = threadIdx.x;
    int tile = blockIdx.x;
    int tx0 = (tile % TILES_X) * TW;
    int ty0 = (tile / TILES_X) * TH;
    int co_base = blockIdx.y * CO_T;
    int b = blockIdx.z;

    int co_grp = tid >> 6;
    int lane = tid & 31;
    int wrp = tid >> 5;
    int r = 2 * ((lane >> 3) & 3) + (wrp & 1);
    int c0 = (lane & 7) << 2;
    int h = c0 >> 1;

    int iy_base = (ty0 >> 1) - 1;
    int jx_base = (tx0 >> 1) - 1;

    ull acc[4][4];
#pragma unroll
    for (int jp = 0; jp < 4; jp++)
#pragma unroll
        for (int p = 0; p < 4; p++) acc[jp][p] = 0ull;

    const float wscale = rsqrtf((float)(CIN * 9));
    const float* in_b = in + (size_t)b * CIN * HIN * HIN;

    for (int cb = 0; cb < CIN; cb += CI_T) {
        __syncthreads();
        for (int idx = tid; idx < CI_T * IR * ICW; idx += 256) {
            int ci = idx / (IR * ICW);
            int rem = idx % (IR * ICW);
            int iy = rem / ICW, ix = rem % ICW;
            int gy = iy_base + iy, gx = jx_base + ix;
            float v = 0.f;
            if (gy >= 0 && gy < HIN && gx >= 0 && gx < HIN)
                v = in_b[(size_t)(cb + ci) * HIN * HIN + gy * HIN + gx];
            s_in[ci][iy][ix] = v;
        }
        for (int idx = tid; idx < CO_T * CI_T * 9; idx += 256) {
            int co = idx / (CI_T * 9);
            int rem = idx % (CI_T * 9);
            int ci = rem / 9, tap = rem % 9;
            s_w[ci][tap][co] =
                wraw[((size_t)(co_base + co) * CIN + cb + ci) * 9 + tap] * wscale;
        }
        __syncthreads();
#pragma unroll
        for (int ci = 0; ci < CI_T; ci++) {
            int ky0 = r & 1;
            for (int ky = ky0; ky < 3; ky += 2) {
                int ir = ((r + ky - 2) >> 1) + 1;
                float x0v = s_in[ci][ir][h];
                float x1v = s_in[ci][ir][h + 1];
                float x2v = s_in[ci][ir][h + 2];
                ull xd0 = pack2(x0v, x0v);
                ull xd1 = pack2(x1v, x1v);
                ull xd2 = pack2(x2v, x2v);
                int wr = (2 - ky) * 3;
#pragma unroll
                for (int jp = 0; jp < 4; jp++) {
                    int co = co_grp * 8 + jp * 2;
                    ull w0 = *reinterpret_cast<const ull*>(&s_w[ci][wr + 0][co]);
                    ull w1 = *reinterpret_cast<const ull*>(&s_w[ci][wr + 1][co]);
                    ull w2 = *reinterpret_cast<const ull*>(&s_w[ci][wr + 2][co]);
                    ffma2(acc[jp][0], w2, xd0);
                    ffma2(acc[jp][0], w0, xd1);
                    ffma2(acc[jp][1], w1, xd1);
                    ffma2(acc[jp][2], w2, xd1);
                    ffma2(acc[jp][2], w0, xd2);
                    ffma2(acc[jp][3], w1, xd2);
                }
            }
        }
    }
    int oy = ty0 + r;
    if (oy >= HOUT) return;
    float* out_b = out + (size_t)b * COUT * HOUT * HOUT;
#pragma unroll
    for (int jp = 0; jp < 4; jp++) {
#pragma unroll
        for (int hh = 0; hh < 2; hh++) {
            int co = co_base + co_grp * 8 + jp * 2 + hh;
            float dm = demod[b * COUT + co];
#pragma unroll
            for (int p = 0; p < 4; p++) {
                float lo, hi;
                unpack2(acc[jp][p], lo, hi);
                float v = (hh ? hi : lo) * dm;
                int ox = tx0 + c0 + p;
                if (ox < HOUT)
                    out_b[(size_t)co * HOUT * HOUT + oy * HOUT + ox] = v;
            }
        }
    }
}

// ---------------- 4x4 blur (pad 1, HIN -> HIN-1) + bias + leaky*sqrt2*style_next
template <int C, int HIN, bool SRC_A>
__global__ __launch_bounds__(256) void blur_kernel(const float* __restrict__ bias,
                                                   int style_id) {
    constexpr int HOUT = HIN - 1;
    constexpr int TH = 16, TW = 32;
    constexpr int TILES_X = HOUT / TW;
    __shared__ float s[TH + 3][TW + 4];

    const float* in = SRC_A ? g_bufA : g_bufB;
    float* out = SRC_A ? g_bufB : g_bufA;

    int tile = blockIdx.x;
    int x0 = (tile % TILES_X) * TW;
    int y0 = (tile / TILES_X) * TH;
    int c = blockIdx.y, b = blockIdx.z;
    const float* ip = in + ((size_t)b * C + c) * HIN * HIN;

    for (int idx = threadIdx.x; idx < (TH + 3) * (TW + 3); idx += 256) {
        int iy = idx / (TW + 3), ix = idx % (TW + 3);
        int gy = y0 + iy - 1, gx = x0 + ix - 1;
        float v = 0.f;
        if (gy >= 0 && gy < HIN && gx >= 0 && gx < HIN) v = ip[gy * HIN + gx];
        s[iy][ix] = v;
    }
    __syncthreads();

    const float c4[4] = {0.25f, 0.75f, 0.75f, 0.25f};
    float bi = bias[c];
    float sn = style_ptr(style_id)[b * C + c];
    float* op = out + ((size_t)b * C + c) * HOUT * HOUT;
#pragma unroll
    for (int q = 0; q < 2; q++) {
        int px = threadIdx.x + q * 256;
        int ly = px >> 5, lx = px & 31;
        float a = 0.f;
#pragma unroll
        for (int ky = 0; ky < 4; ky++) {
            float rs = 0.f;
#pragma unroll
            for (int kx = 0; kx < 4; kx++) rs += c4[kx] * s[ly + ky][lx + kx];
            a += c4[ky] * rs;
        }
        a += bi;
        a = (a > 0.f ? a : 0.2f * a) * 1.41421356237309515f * sn;
        op[(y0 + ly) * HOUT + x0 + lx] = a;
    }
}

// ---------------- final 1x1 (32 -> 3 of 4 ch), no demod, + out_bias ---------
__global__ void final_kernel(const float* __restrict__ finw,
                             const float* __restrict__ outb,
                             float* __restrict__ out) {
    int idx = blockIdx.x * blockDim.x + threadIdx.x;  // over 16*16384
    int b = idx >> 14;
    int p = idx & 16383;
    const float* ib = g_bufB + (size_t)b * 32 * 16384 + p;
    float a0 = 0.f, a1 = 0.f, a2 = 0.f;
#pragma unroll
    for (int ci = 0; ci < 32; ci++) {
        float v = ib[(size_t)ci * 16384];
        a0 = fmaf(finw[ci], v, a0);
        a1 = fmaf(finw[32 + ci], v, a1);
        a2 = fmaf(finw[64 + ci], v, a2);
    }
    const float sc = rsqrtf(32.0f);
    out[(size_t)b * 3 * 16384 + p] = a0 * sc + outb[0];
    out[(size_t)b * 3 * 16384 + 16384 + p] = a1 * sc + outb[1];
    out[(size_t)b * 3 * 16384 + 2 * 16384 + p] = a2 * sc + outb[2];
}

// ------------------------------------------------------------------------
extern "C" void kernel_launch(void* const* d_in, const int* in_sizes, int n_in,
                              void* d_out, int out_size) {
    (void)in_sizes; (void)n_in; (void)out_size;
    const float* fg = (const float*)d_in[0];
    const float* mask = (const float*)d_in[1];
    const float* bg = (const float*)d_in[2];
    const float* z = (const float*)d_in[3];
    const float* l_w[5]  = {(const float*)d_in[4],  (const float*)d_in[8],
                            (const float*)d_in[12], (const float*)d_in[16],
                            (const float*)d_in[20]};
    const float* l_mw[5] = {(const float*)d_in[5],  (const float*)d_in[9],
                            (const float*)d_in[13], (const float*)d_in[17],
                            (const float*)d_in[21]};
    const float* l_mb[5] = {(const float*)d_in[6],  (const float*)d_in[10],
                            (const float*)d_in[14], (const float*)d_in[18],
                            (const float*)d_in[22]};
    const float* l_b[5]  = {(const float*)d_in[7],  (const float*)d_in[11],
                            (const float*)d_in[15], (const float*)d_in[19],
                            (const float*)d_in[23]};
    const float* finw = (const float*)d_in[24];
    const float* fin_mw = (const float*)d_in[25];
    const float* fin_mb = (const float*)d_in[26];
    const float* outb = (const float*)d_in[27];

    // fused setup: 2 kernels total (styles; demod with inline wsq)
    P6 mw6, mb6;
    for (int l = 0; l < 5; l++) { mw6.a[l] = l_mw[l]; mb6.a[l] = l_mb[l]; }
    mw6.a[5] = fin_mw; mb6.a[5] = fin_mb;
    style_all_kernel<<<1344, 256>>>(z, mw6, mb6);
    P5 w5;
    for (int l = 0; l < 5; l++) w5.a[l] = l_w[l];
    demod_all_kernel<<<832, 256>>>(w5);

    // compose + modulate for layer 0 -> bufA   (launch #3)
    compose_kernel<<<(NB * 256 * 1024) / 256, 256>>>(fg, mask, bg);

    // l0: 256->128 @32x32   (A -> B)   (launch #4 — ncu capture target)
    conv3x3_kernel<256, 128, 32, 32, true><<<dim3(4, 4, NB), 256>>>(l_w[0], l_b[0], 0, 1);
    // l1: tconv 128->128, 32 -> 65   (B -> A)
    tconv_kernel<128, 128, 32, false><<<dim3(27, 4, NB), 256>>>(l_w[1], 1);
    // blur 65 -> 64 + act + style2   (A -> B)
    blur_kernel<128, 65, true><<<dim3(8, 128, NB), 256>>>(l_b[1], 2);
    // l2: 128->64 @64x64   (B -> A)
    conv3x3_kernel<128, 64, 64, 64, false><<<dim3(16, 2, NB), 256>>>(l_w[2], l_b[2], 2, 3);
    // l3: tconv 64->64, 64 -> 129   (A -> B)
    tconv_kernel<64, 64, 64, true><<<dim3(85, 2, NB), 256>>>(l_w[3], 3);
    // blur 129 -> 128 + act + style4   (B -> A)
    blur_kernel<64, 129, false><<<dim3(32, 64, NB), 256>>>(l_b[3], 4);
    // l4: 64->32 @128x128   (A -> B)
    conv3x3_kernel<64, 32, 128, 128, true><<<dim3(64, 1, NB), 256>>>(l_w[4], l_b[4], 4, 5);
    // final 1x1 32->3 + out_bias   (B -> d_out)
    final_kernel<<<(NB * 16384) / 256, 256>>>(finw, outb, (float*)d_out);
}

// round 9
// speedup vs baseline: 1.1701x; 1.1294x over previous
#include <cuda_runtime.h>
#include <math.h>

#define NB 16
#define SDIM 512

typedef unsigned long long ull;

__device__ __forceinline__ ull pack2(float a, float b) {
    ull r;
    asm("mov.b64 %0, {%1, %2};" : "=l"(r) : "f"(a), "f"(b));
    return r;
}
__device__ __forceinline__ void unpack2(ull v, float& a, float& b) {
    asm("mov.b64 {%0, %1}, %2;" : "=f"(a), "=f"(b) : "l"(v));
}
__device__ __forceinline__ void ffma2(ull& d, ull a, ull b) {
    asm("fma.rn.f32x2 %0, %1, %2, %0;" : "+l"(d) : "l"(a), "l"(b));
}

// ---------------- persistent scratch (no allocs allowed) ----------------
static __device__ float g_bufA[16777216];   // max: (16,64,128,128)
static __device__ float g_bufB[17040384];   // max: (16,64,129,129)

static __device__ float g_style0[NB * 256];
static __device__ float g_style1[NB * 128];
static __device__ float g_style2[NB * 128];
static __device__ float g_style3[NB * 64];
static __device__ float g_style4[NB * 64];
static __device__ float g_stylef[NB * 32];

static __device__ float g_demod0[NB * 128];
static __device__ float g_demod1[NB * 128];
static __device__ float g_demod2[NB * 64];
static __device__ float g_demod3[NB * 64];
static __device__ float g_demod4[NB * 32];

__device__ __forceinline__ float* style_ptr(int id) {
    switch (id) {
        case 0: return g_style0;
        case 1: return g_style1;
        case 2: return g_style2;
        case 3: return g_style3;
        case 4: return g_style4;
        default: return g_stylef;
    }
}
__device__ __forceinline__ float* demod_ptr(int id) {
    switch (id) {
        case 0: return g_demod0;
        case 1: return g_demod1;
        case 2: return g_demod2;
        case 3: return g_demod3;
        default: return g_demod4;
    }
}

struct P6 { const float* a[6]; };
struct P5 { const float* a[5]; };

// ---------------- fused style kernel: all 6 layers ----------------
__global__ void style_all_kernel(const float* __restrict__ z, P6 mw, P6 mb) {
    int gw = blockIdx.x * 8 + (threadIdx.x >> 5);
    int lane = threadIdx.x & 31;
    if (gw >= NB * 672) return;
    int b = gw / 672;
    int c = gw - b * 672;
    int L, ci, Ci;
    if (c < 256)      { L = 0; ci = c;       Ci = 256; }
    else if (c < 384) { L = 1; ci = c - 256; Ci = 128; }
    else if (c < 512) { L = 2; ci = c - 384; Ci = 128; }
    else if (c < 576) { L = 3; ci = c - 512; Ci = 64; }
    else if (c < 640) { L = 4; ci = c - 576; Ci = 64; }
    else              { L = 5; ci = c - 640; Ci = 32; }
    const float* zr = z + b * SDIM;
    const float* mr = mw.a[L] + (size_t)ci * SDIM;
    float s = 0.f;
#pragma unroll 4
    for (int k = lane; k < SDIM; k += 32) s += zr[k] * mr[k];
#pragma unroll
    for (int o = 16; o; o >>= 1) s += __shfl_xor_sync(0xffffffffu, s, o);
    if (lane == 0)
        style_ptr(L)[b * Ci + ci] = s * 0.04419417382415922f + mb.a[L][ci];
}

// ---------------- fused demod kernel, wsq inline ----------------
__global__ void demod_all_kernel(P5 w) {
    int gw = blockIdx.x * 8 + (threadIdx.x >> 5);
    int lane = threadIdx.x & 31;
    if (gw >= NB * 416) return;
    int b = gw / 416;
    int c = gw - b * 416;
    int L, co, Co, Ci;
    if (c < 128)      { L = 0; co = c;       Co = 128; Ci = 256; }
    else if (c < 256) { L = 1; co = c - 128; Co = 128; Ci = 128; }
    else if (c < 320) { L = 2; co = c - 256; Co = 64;  Ci = 128; }
    else if (c < 384) { L = 3; co = c - 320; Co = 64;  Ci = 64; }
    else              { L = 4; co = c - 384; Co = 32;  Ci = 64; }
    const float* st = style_ptr(L) + b * Ci;
    const float* wb = w.a[L] + (size_t)co * Ci * 9;
    float s = 0.f;
    for (int ci = lane; ci < Ci; ci += 32) {
        const float* p = wb + ci * 9;
        float wq = 0.f;
#pragma unroll
        for (int t = 0; t < 9; t++) wq += p[t] * p[t];
        float sv = st[ci];
        s += sv * sv * wq;
    }
#pragma unroll
    for (int o = 16; o; o >>= 1) s += __shfl_xor_sync(0xffffffffu, s, o);
    if (lane == 0)
        demod_ptr(L)[b * Co + co] = rsqrtf(s * (1.0f / (float)(Ci * 9)) + 1e-8f);
}

// ---------------- compose: bufA = (fg + (1-mask)*bg) * style0 ----------------
__global__ void compose_kernel(const float* __restrict__ fg,
                               const float* __restrict__ mask,
                               const float* __restrict__ bg) {
    int idx = blockIdx.x * blockDim.x + threadIdx.x;
    int p = idx & 1023;
    int c = (idx >> 10) & 255;
    int b = idx >> 18;
    float m = 1.0f - mask[b * 1024 + p];
    float v = fg[idx] + m * bg[idx];
    g_bufA[idx] = v * g_style0[b * 256 + c];
}

// ---------------- 3x3 conv, pad 1, f32x2-packed; CO_T templated ------------
// W_LD = CO_T+2: kills the 32-way STS bank conflict in weight staging.
template <int CIN, int COUT, int H, int W, bool SRC_A, int CO_T>
__global__ __launch_bounds__(256) void conv3x3_kernel(const float* __restrict__ wraw,
                                                      const float* __restrict__ bias,
                                                      int demod_id, int style_id) {
    constexpr int CI_T = 8, TH = 8, TW = 32;
    constexpr int CO_PW = CO_T / 8;   // co per warp (2 or 4)
    constexpr int JP = CO_PW / 2;     // f32x2 pairs per warp (1 or 2)
    constexpr int IN_LD = 36;
    constexpr int W_LD = CO_T + 2;    // conflict-free staging, 8B-aligned rows
    constexpr int TILES_X = W / TW;
    __shared__ __align__(16) float s_in[CI_T][TH + 2][IN_LD];
    __shared__ __align__(16) float s_w[CI_T][9][W_LD];

    const float* in = SRC_A ? g_bufA : g_bufB;
    float* out = SRC_A ? g_bufB : g_bufA;
    const float* demod = demod_ptr(demod_id);
    const float* styn = style_ptr(style_id);

    int tid = threadIdx.x;
    int tile = blockIdx.x;
    int tx0 = (tile % TILES_X) * TW;
    int ty0 = (tile / TILES_X) * TH;
    int co_base = blockIdx.y * CO_T;
    int b = blockIdx.z;

    int warp = tid >> 5;          // 0..7 -> CO_PW consecutive co
    int lane = tid & 31;
    int r = lane >> 2;            // 0..7
    int c0 = (lane & 3) << 3;     // 0,8,16,24

    ull acc[JP][8];
#pragma unroll
    for (int jp = 0; jp < JP; jp++)
#pragma unroll
        for (int p = 0; p < 8; p++) acc[jp][p] = 0ull;

    const float wscale = rsqrtf((float)(CIN * 9));
    const float* in_b = in + (size_t)b * CIN * H * W;

    for (int cb = 0; cb < CIN; cb += CI_T) {
        __syncthreads();
        // input tile (with halo), zero-padded at edges
        for (int idx = tid; idx < CI_T * (TH + 2) * 34; idx += 256) {
            int ci = idx / ((TH + 2) * 34);
            int rem = idx % ((TH + 2) * 34);
            int iy = rem / 34, ix = rem % 34;
            int gy = ty0 + iy - 1, gx = tx0 + ix - 1;
            float v = 0.f;
            if (gy >= 0 && gy < H && gx >= 0 && gx < W)
                v = in_b[(size_t)(cb + ci) * H * W + gy * W + gx];
            s_in[ci][iy][ix] = v;
        }
        // weights (pre-scaled)
        for (int idx = tid; idx < CO_T * CI_T * 9; idx += 256) {
            int co = idx / (CI_T * 9);
            int rem = idx % (CI_T * 9);
            int ci = rem / 9, tap = rem % 9;
            s_w[ci][tap][co] =
                wraw[((size_t)(co_base + co) * CIN + cb + ci) * 9 + tap] * wscale;
        }
        __syncthreads();
#pragma unroll
        for (int ci = 0; ci < CI_T; ci++) {
#pragma unroll
            for (int ky = 0; ky < 3; ky++) {
                const float4* row4 =
                    reinterpret_cast<const float4*>(&s_in[ci][r + ky][c0]);
                float4 q0 = row4[0];
                float4 q1 = row4[1];
                float4 q2 = row4[2];
                ull xd[10];
                xd[0] = pack2(q0.x, q0.x); xd[1] = pack2(q0.y, q0.y);
                xd[2] = pack2(q0.z, q0.z); xd[3] = pack2(q0.w, q0.w);
                xd[4] = pack2(q1.x, q1.x); xd[5] = pack2(q1.y, q1.y);
                xd[6] = pack2(q1.z, q1.z); xd[7] = pack2(q1.w, q1.w);
                xd[8] = pack2(q2.x, q2.x); xd[9] = pack2(q2.y, q2.y);
#pragma unroll
                for (int kx = 0; kx < 3; kx++) {
#pragma unroll
                    for (int jp = 0; jp < JP; jp++) {
                        ull w2 = *reinterpret_cast<const ull*>(
                            &s_w[ci][ky * 3 + kx][warp * CO_PW + jp * 2]);
#pragma unroll
                        for (int p = 0; p < 8; p++) ffma2(acc[jp][p], w2, xd[kx + p]);
                    }
                }
            }
        }
    }
    // epilogue
    int oy = ty0 + r;
    float* out_b = out + (size_t)b * COUT * H * W;
#pragma unroll
    for (int jp = 0; jp < JP; jp++) {
        float vlo[8], vhi[8];
#pragma unroll
        for (int p = 0; p < 8; p++) unpack2(acc[jp][p], vlo[p], vhi[p]);
#pragma unroll
        for (int h = 0; h < 2; h++) {
            int co = co_base + warp * CO_PW + jp * 2 + h;
            float dm = demod[b * COUT + co];
            float bi = bias[co];
            float sn = styn[b * COUT + co];
            float* op = out_b + (size_t)co * H * W + oy * W + tx0 + c0;
            const float* src = h ? vhi : vlo;
            float4 o0, o1;
            float vv[8];
#pragma unroll
            for (int p = 0; p < 8; p++) {
                float v = src[p] * dm + bi;
                vv[p] = (v > 0.f ? v : 0.2f * v) * 1.41421356237309515f * sn;
            }
            o0.x = vv[0]; o0.y = vv[1]; o0.z = vv[2]; o0.w = vv[3];
            o1.x = vv[4]; o1.y = vv[5]; o1.z = vv[6]; o1.w = vv[7];
            reinterpret_cast<float4*>(op)[0] = o0;
            reinterpret_cast<float4*>(op)[1] = o1;
        }
    }
}

// ---------------- transposed conv (W_LD padded; otherwise best-known) -------
template <int CIN, int COUT, int HIN, bool SRC_A>
__global__ __launch_bounds__(256) void tconv_kernel(const float* __restrict__ wraw,
                                                    int demod_id) {
    constexpr int HOUT = 2 * HIN + 1;
    constexpr int CO_T = 32, CI_T = 8, TH = 8, TW = 32;
    constexpr int IR = 6, ICW = 18, IC_LD = 19;
    constexpr int W_LD = 34;   // kills 32-way STS conflict; rows stay 8B-aligned
    constexpr int TILES_X = (HOUT + TW - 1) / TW;
    __shared__ __align__(16) float s_in[CI_T][IR][IC_LD];
    __shared__ __align__(16) float s_w[CI_T][9][W_LD];

    const float* in = SRC_A ? g_bufA : g_bufB;
    float* out = SRC_A ? g_bufB : g_bufA;
    const float* demod = demod_ptr(demod_id);

    int tid = threadIdx.x;
    int tile = blockIdx.x;
    int tx0 = (tile % TILES_X) * TW;
    int ty0 = (tile / TILES_X) * TH;
    int co_base = blockIdx.y * CO_T;
    int b = blockIdx.z;

    int co_grp = tid >> 6;
    int lane = tid & 31;
    int wrp = tid >> 5;
    int r = 2 * ((lane >> 3) & 3) + (wrp & 1);
    int c0 = (lane & 7) << 2;
    int h = c0 >> 1;

    int iy_base = (ty0 >> 1) - 1;
    int jx_base = (tx0 >> 1) - 1;

    ull acc[4][4];
#pragma unroll
    for (int jp = 0; jp < 4; jp++)
#pragma unroll
        for (int p = 0; p < 4; p++) acc[jp][p] = 0ull;

    const float wscale = rsqrtf((float)(CIN * 9));
    const float* in_b = in + (size_t)b * CIN * HIN * HIN;

    for (int cb = 0; cb < CIN; cb += CI_T) {
        __syncthreads();
        for (int idx = tid; idx < CI_T * IR * ICW; idx += 256) {
            int ci = idx / (IR * ICW);
            int rem = idx % (IR * ICW);
            int iy = rem / ICW, ix = rem % ICW;
            int gy = iy_base + iy, gx = jx_base + ix;
            float v = 0.f;
            if (gy >= 0 && gy < HIN && gx >= 0 && gx < HIN)
                v = in_b[(size_t)(cb + ci) * HIN * HIN + gy * HIN + gx];
            s_in[ci][iy][ix] = v;
        }
        for (int idx = tid; idx < CO_T * CI_T * 9; idx += 256) {
            int co = idx / (CI_T * 9);
            int rem = idx % (CI_T * 9);
            int ci = rem / 9, tap = rem % 9;
            s_w[ci][tap][co] =
                wraw[((size_t)(co_base + co) * CIN + cb + ci) * 9 + tap] * wscale;
        }
        __syncthreads();
#pragma unroll
        for (int ci = 0; ci < CI_T; ci++) {
            int ky0 = r & 1;
            for (int ky = ky0; ky < 3; ky += 2) {
                int ir = ((r + ky - 2) >> 1) + 1;
                float x0v = s_in[ci][ir][h];
                float x1v = s_in[ci][ir][h + 1];
                float x2v = s_in[ci][ir][h + 2];
                ull xd0 = pack2(x0v, x0v);
                ull xd1 = pack2(x1v, x1v);
                ull xd2 = pack2(x2v, x2v);
                int wr = (2 - ky) * 3;
#pragma unroll
                for (int jp = 0; jp < 4; jp++) {
                    int co = co_grp * 8 + jp * 2;
                    ull w0 = *reinterpret_cast<const ull*>(&s_w[ci][wr + 0][co]);
                    ull w1 = *reinterpret_cast<const ull*>(&s_w[ci][wr + 1][co]);
                    ull w2 = *reinterpret_cast<const ull*>(&s_w[ci][wr + 2][co]);
                    ffma2(acc[jp][0], w2, xd0);
                    ffma2(acc[jp][0], w0, xd1);
                    ffma2(acc[jp][1], w1, xd1);
                    ffma2(acc[jp][2], w2, xd1);
                    ffma2(acc[jp][2], w0, xd2);
                    ffma2(acc[jp][3], w1, xd2);
                }
            }
        }
    }
    int oy = ty0 + r;
    if (oy >= HOUT) return;
    float* out_b = out + (size_t)b * COUT * HOUT * HOUT;
#pragma unroll
    for (int jp = 0; jp < 4; jp++) {
#pragma unroll
        for (int hh = 0; hh < 2; hh++) {
            int co = co_base + co_grp * 8 + jp * 2 + hh;
            float dm = demod[b * COUT + co];
#pragma unroll
            for (int p = 0; p < 4; p++) {
                float lo, hi;
                unpack2(acc[jp][p], lo, hi);
                float v = (hh ? hi : lo) * dm;
                int ox = tx0 + c0 + p;
                if (ox < HOUT)
                    out_b[(size_t)co * HOUT * HOUT + oy * HOUT + ox] = v;
            }
        }
    }
}

// ---------------- 4x4 blur + bias + leaky*sqrt2*style_next ----------------
template <int C, int HIN, bool SRC_A>
__global__ __launch_bounds__(256) void blur_kernel(const float* __restrict__ bias,
                                                   int style_id) {
    constexpr int HOUT = HIN - 1;
    constexpr int TH = 16, TW = 32;
    constexpr int TILES_X = HOUT / TW;
    __shared__ float s[TH + 3][TW + 4];

    const float* in = SRC_A ? g_bufA : g_bufB;
    float* out = SRC_A ? g_bufB : g_bufA;

    int tile = blockIdx.x;
    int x0 = (tile % TILES_X) * TW;
    int y0 = (tile / TILES_X) * TH;
    int c = blockIdx.y, b = blockIdx.z;
    const float* ip = in + ((size_t)b * C + c) * HIN * HIN;

    for (int idx = threadIdx.x; idx < (TH + 3) * (TW + 3); idx += 256) {
        int iy = idx / (TW + 3), ix = idx % (TW + 3);
        int gy = y0 + iy - 1, gx = x0 + ix - 1;
        float v = 0.f;
        if (gy >= 0 && gy < HIN && gx >= 0 && gx < HIN) v = ip[gy * HIN + gx];
        s[iy][ix] = v;
    }
    __syncthreads();

    const float c4[4] = {0.25f, 0.75f, 0.75f, 0.25f};
    float bi = bias[c];
    float sn = style_ptr(style_id)[b * C + c];
    float* op = out + ((size_t)b * C + c) * HOUT * HOUT;
#pragma unroll
    for (int q = 0; q < 2; q++) {
        int px = threadIdx.x + q * 256;
        int ly = px >> 5, lx = px & 31;
        float a = 0.f;
#pragma unroll
        for (int ky = 0; ky < 4; ky++) {
            float rs = 0.f;
#pragma unroll
            for (int kx = 0; kx < 4; kx++) rs += c4[kx] * s[ly + ky][lx + kx];
            a += c4[ky] * rs;
        }
        a += bi;
        a = (a > 0.f ? a : 0.2f * a) * 1.41421356237309515f * sn;
        op[(y0 + ly) * HOUT + x0 + lx] = a;
    }
}

// ---------------- final 1x1 (32 -> 3 of 4 ch), + out_bias ----------------
__global__ void final_kernel(const float* __restrict__ finw,
                             const float* __restrict__ outb,
                             float* __restrict__ out) {
    int idx = blockIdx.x * blockDim.x + threadIdx.x;
    int b = idx >> 14;
    int p = idx & 16383;
    const float* ib = g_bufB + (size_t)b * 32 * 16384 + p;
    float a0 = 0.f, a1 = 0.f, a2 = 0.f;
#pragma unroll
    for (int ci = 0; ci < 32; ci++) {
        float v = ib[(size_t)ci * 16384];
        a0 = fmaf(finw[ci], v, a0);
        a1 = fmaf(finw[32 + ci], v, a1);
        a2 = fmaf(finw[64 + ci], v, a2);
    }
    const float sc = rsqrtf(32.0f);
    out[(size_t)b * 3 * 16384 + p] = a0 * sc + outb[0];
    out[(size_t)b * 3 * 16384 + 16384 + p] = a1 * sc + outb[1];
    out[(size_t)b * 3 * 16384 + 2 * 16384 + p] = a2 * sc + outb[2];
}

// ------------------------------------------------------------------------
extern "C" void kernel_launch(void* const* d_in, const int* in_sizes, int n_in,
                              void* d_out, int out_size) {
    (void)in_sizes; (void)n_in; (void)out_size;
    const float* fg = (const float*)d_in[0];
    const float* mask = (const float*)d_in[1];
    const float* bg = (const float*)d_in[2];
    const float* z = (const float*)d_in[3];
    const float* l_w[5]  = {(const float*)d_in[4],  (const float*)d_in[8],
                            (const float*)d_in[12], (const float*)d_in[16],
                            (const float*)d_in[20]};
    const float* l_mw[5] = {(const float*)d_in[5],  (const float*)d_in[9],
                            (const float*)d_in[13], (const float*)d_in[17],
                            (const float*)d_in[21]};
    const float* l_mb[5] = {(const float*)d_in[6],  (const float*)d_in[10],
                            (const float*)d_in[14], (const float*)d_in[18],
                            (const float*)d_in[22]};
    const float* l_b[5]  = {(const float*)d_in[7],  (const float*)d_in[11],
                            (const float*)d_in[15], (const float*)d_in[19],
                            (const float*)d_in[23]};
    const float* finw = (const float*)d_in[24];
    const float* fin_mw = (const float*)d_in[25];
    const float* fin_mb = (const float*)d_in[26];
    const float* outb = (const float*)d_in[27];

    // fused setup: 2 kernels
    P6 mw6, mb6;
    for (int l = 0; l < 5; l++) { mw6.a[l] = l_mw[l]; mb6.a[l] = l_mb[l]; }
    mw6.a[5] = fin_mw; mb6.a[5] = fin_mb;
    style_all_kernel<<<1344, 256>>>(z, mw6, mb6);
    P5 w5;
    for (int l = 0; l < 5; l++) w5.a[l] = l_w[l];
    demod_all_kernel<<<832, 256>>>(w5);

    // compose + modulate for layer 0 -> bufA
    compose_kernel<<<(NB * 256 * 1024) / 256, 256>>>(fg, mask, bg);

    // l0: 256->128 @32x32 (A -> B), CO_T=16 -> 512 CTAs
    conv3x3_kernel<256, 128, 32, 32, true, 16>
        <<<dim3(4, 8, NB), 256>>>(l_w[0], l_b[0], 0, 1);
    // l1: tconv 128->128, 32 -> 65   (B -> A)
    tconv_kernel<128, 128, 32, false><<<dim3(27, 4, NB), 256>>>(l_w[1], 1);
    // blur 65 -> 64 + act + style2   (A -> B)
    blur_kernel<128, 65, true><<<dim3(8, 128, NB), 256>>>(l_b[1], 2);
    // l2: 128->64 @64x64   (B -> A)
    conv3x3_kernel<128, 64, 64, 64, false, 32>
        <<<dim3(16, 2, NB), 256>>>(l_w[2], l_b[2], 2, 3);
    // l3: tconv 64->64, 64 -> 129   (A -> B)
    tconv_kernel<64, 64, 64, true><<<dim3(85, 2, NB), 256>>>(l_w[3], 3);
    // blur 129 -> 128 + act + style4   (B -> A)
    blur_kernel<64, 129, false><<<dim3(32, 64, NB), 256>>>(l_b[3], 4);
    // l4: 64->32 @128x128   (A -> B)
    conv3x3_kernel<64, 32, 128, 128, true, 32>
        <<<dim3(64, 1, NB), 256>>>(l_w[4], l_b[4], 4, 5);
    // final 1x1 32->3 + out_bias   (B -> d_out)
    final_kernel<<<(NB * 16384) / 256, 256>>>(finw, outb, (float*)d_out);
}

// round 10
// speedup vs baseline: 1.2193x; 1.0420x over previous
#include <cuda_runtime.h>
#include <math.h>

#define NB 16
#define SDIM 512

typedef unsigned long long ull;

__device__ __forceinline__ ull pack2(float a, float b) {
    ull r;
    asm("mov.b64 %0, {%1, %2};" : "=l"(r) : "f"(a), "f"(b));
    return r;
}
__device__ __forceinline__ void unpack2(ull v, float& a, float& b) {
    asm("mov.b64 {%0, %1}, %2;" : "=f"(a), "=f"(b) : "l"(v));
}
__device__ __forceinline__ void ffma2(ull& d, ull a, ull b) {
    asm("fma.rn.f32x2 %0, %1, %2, %0;" : "+l"(d) : "l"(a), "l"(b));
}

// ---------------- persistent scratch (no allocs allowed) ----------------
static __device__ float g_bufA[16777216];   // max: (16,64,128,128)
static __device__ float g_bufB[17040384];   // max: (16,64,129,129)
static __device__ float g_part[4194304];    // l0 split-K partials: [2][16][128][1024]

static __device__ float g_style0[NB * 256];
static __device__ float g_style1[NB * 128];
static __device__ float g_style2[NB * 128];
static __device__ float g_style3[NB * 64];
static __device__ float g_style4[NB * 64];
static __device__ float g_stylef[NB * 32];

static __device__ float g_demod0[NB * 128];
static __device__ float g_demod1[NB * 128];
static __device__ float g_demod2[NB * 64];
static __device__ float g_demod3[NB * 64];
static __device__ float g_demod4[NB * 32];

__device__ __forceinline__ float* style_ptr(int id) {
    switch (id) {
        case 0: return g_style0;
        case 1: return g_style1;
        case 2: return g_style2;
        case 3: return g_style3;
        case 4: return g_style4;
        default: return g_stylef;
    }
}
__device__ __forceinline__ float* demod_ptr(int id) {
    switch (id) {
        case 0: return g_demod0;
        case 1: return g_demod1;
        case 2: return g_demod2;
        case 3: return g_demod3;
        default: return g_demod4;
    }
}

struct P6 { const float* a[6]; };
struct P5 { const float* a[5]; };

// ---------------- fused style kernel: all 6 layers ----------------
__global__ void style_all_kernel(const float* __restrict__ z, P6 mw, P6 mb) {
    int gw = blockIdx.x * 8 + (threadIdx.x >> 5);
    int lane = threadIdx.x & 31;
    if (gw >= NB * 672) return;
    int b = gw / 672;
    int c = gw - b * 672;
    int L, ci, Ci;
    if (c < 256)      { L = 0; ci = c;       Ci = 256; }
    else if (c < 384) { L = 1; ci = c - 256; Ci = 128; }
    else if (c < 512) { L = 2; ci = c - 384; Ci = 128; }
    else if (c < 576) { L = 3; ci = c - 512; Ci = 64; }
    else if (c < 640) { L = 4; ci = c - 576; Ci = 64; }
    else              { L = 5; ci = c - 640; Ci = 32; }
    const float* zr = z + b * SDIM;
    const float* mr = mw.a[L] + (size_t)ci * SDIM;
    float s = 0.f;
#pragma unroll 4
    for (int k = lane; k < SDIM; k += 32) s += zr[k] * mr[k];
#pragma unroll
    for (int o = 16; o; o >>= 1) s += __shfl_xor_sync(0xffffffffu, s, o);
    if (lane == 0)
        style_ptr(L)[b * Ci + ci] = s * 0.04419417382415922f + mb.a[L][ci];
}

// ---------------- fused demod kernel, wsq inline ----------------
__global__ void demod_all_kernel(P5 w) {
    int gw = blockIdx.x * 8 + (threadIdx.x >> 5);
    int lane = threadIdx.x & 31;
    if (gw >= NB * 416) return;
    int b = gw / 416;
    int c = gw - b * 416;
    int L, co, Co, Ci;
    if (c < 128)      { L = 0; co = c;       Co = 128; Ci = 256; }
    else if (c < 256) { L = 1; co = c - 128; Co = 128; Ci = 128; }
    else if (c < 320) { L = 2; co = c - 256; Co = 64;  Ci = 128; }
    else if (c < 384) { L = 3; co = c - 320; Co = 64;  Ci = 64; }
    else              { L = 4; co = c - 384; Co = 32;  Ci = 64; }
    const float* st = style_ptr(L) + b * Ci;
    const float* wb = w.a[L] + (size_t)co * Ci * 9;
    float s = 0.f;
    for (int ci = lane; ci < Ci; ci += 32) {
        const float* p = wb + ci * 9;
        float wq = 0.f;
#pragma unroll
        for (int t = 0; t < 9; t++) wq += p[t] * p[t];
        float sv = st[ci];
        s += sv * sv * wq;
    }
#pragma unroll
    for (int o = 16; o; o >>= 1) s += __shfl_xor_sync(0xffffffffu, s, o);
    if (lane == 0)
        demod_ptr(L)[b * Co + co] = rsqrtf(s * (1.0f / (float)(Ci * 9)) + 1e-8f);
}

// ---------------- compose: bufA = (fg + (1-mask)*bg) * style0 ----------------
__global__ void compose_kernel(const float* __restrict__ fg,
                               const float* __restrict__ mask,
                               const float* __restrict__ bg) {
    int idx = blockIdx.x * blockDim.x + threadIdx.x;
    int p = idx & 1023;
    int c = (idx >> 10) & 255;
    int b = idx >> 18;
    float m = 1.0f - mask[b * 1024 + p];
    float v = fg[idx] + m * bg[idx];
    g_bufA[idx] = v * g_style0[b * 256 + c];
}

// ---------------- 3x3 conv, pad 1, f32x2-packed; optional split-K -----------
// PARTIAL: compute CIN_DO channels from cin_off = half*CIN_DO; store raw accs
// to g_part[half][b][co][hw]. Otherwise full conv + styled epilogue.
template <int CIN_TOT, int CIN_DO, int COUT, int H, int W, bool SRC_A, int CO_T,
          bool PARTIAL>
__global__ __launch_bounds__(256) void conv3x3_kernel(const float* __restrict__ wraw,
                                                      const float* __restrict__ bias,
                                                      int demod_id, int style_id) {
    constexpr int CI_T = 8, TH = 8, TW = 32;
    constexpr int CO_PW = CO_T / 8;
    constexpr int JP = CO_PW / 2;
    constexpr int IN_LD = 36;
    constexpr int W_LD = CO_T + 2;
    constexpr int TILES_X = W / TW;
    __shared__ __align__(16) float s_in[CI_T][TH + 2][IN_LD];
    __shared__ __align__(16) float s_w[CI_T][9][W_LD];

    const float* in = SRC_A ? g_bufA : g_bufB;
    float* out = SRC_A ? g_bufB : g_bufA;
    const float* demod = demod_ptr(demod_id);
    const float* styn = style_ptr(style_id);

    int tid = threadIdx.x;
    int tile = blockIdx.x;
    int tx0 = (tile % TILES_X) * TW;
    int ty0 = (tile / TILES_X) * TH;
    int co_base = blockIdx.y * CO_T;

    int b, half, cin_off;
    if (PARTIAL) {
        b = blockIdx.z >> 1;
        half = blockIdx.z & 1;
        cin_off = half * CIN_DO;
    } else {
        b = blockIdx.z;
        half = 0;
        cin_off = 0;
    }

    int warp = tid >> 5;
    int lane = tid & 31;
    int r = lane >> 2;
    int c0 = (lane & 3) << 3;

    ull acc[JP][8];
#pragma unroll
    for (int jp = 0; jp < JP; jp++)
#pragma unroll
        for (int p = 0; p < 8; p++) acc[jp][p] = 0ull;

    const float wscale = rsqrtf((float)(CIN_TOT * 9));
    const float* in_b = in + (size_t)b * CIN_TOT * H * W;

    for (int cb = 0; cb < CIN_DO; cb += CI_T) {
        __syncthreads();
        // input tile (with halo), zero-padded at edges
        for (int idx = tid; idx < CI_T * (TH + 2) * 34; idx += 256) {
            int ci = idx / ((TH + 2) * 34);
            int rem = idx % ((TH + 2) * 34);
            int iy = rem / 34, ix = rem % 34;
            int gy = ty0 + iy - 1, gx = tx0 + ix - 1;
            float v = 0.f;
            if (gy >= 0 && gy < H && gx >= 0 && gx < W)
                v = in_b[(size_t)(cin_off + cb + ci) * H * W + gy * W + gx];
            s_in[ci][iy][ix] = v;
        }
        // weights (pre-scaled)
        for (int idx = tid; idx < CO_T * CI_T * 9; idx += 256) {
            int co = idx / (CI_T * 9);
            int rem = idx % (CI_T * 9);
            int ci = rem / 9, tap = rem % 9;
            s_w[ci][tap][co] =
                wraw[((size_t)(co_base + co) * CIN_TOT + cin_off + cb + ci) * 9 +
                     tap] * wscale;
        }
        __syncthreads();
#pragma unroll
        for (int ci = 0; ci < CI_T; ci++) {
#pragma unroll
            for (int ky = 0; ky < 3; ky++) {
                const float4* row4 =
                    reinterpret_cast<const float4*>(&s_in[ci][r + ky][c0]);
                float4 q0 = row4[0];
                float4 q1 = row4[1];
                float4 q2 = row4[2];
                ull xd[10];
                xd[0] = pack2(q0.x, q0.x); xd[1] = pack2(q0.y, q0.y);
                xd[2] = pack2(q0.z, q0.z); xd[3] = pack2(q0.w, q0.w);
                xd[4] = pack2(q1.x, q1.x); xd[5] = pack2(q1.y, q1.y);
                xd[6] = pack2(q1.z, q1.z); xd[7] = pack2(q1.w, q1.w);
                xd[8] = pack2(q2.x, q2.x); xd[9] = pack2(q2.y, q2.y);
#pragma unroll
                for (int kx = 0; kx < 3; kx++) {
#pragma unroll
                    for (int jp = 0; jp < JP; jp++) {
                        ull w2 = *reinterpret_cast<const ull*>(
                            &s_w[ci][ky * 3 + kx][warp * CO_PW + jp * 2]);
#pragma unroll
                        for (int p = 0; p < 8; p++) ffma2(acc[jp][p], w2, xd[kx + p]);
                    }
                }
            }
        }
    }
    int oy = ty0 + r;
#pragma unroll
    for (int jp = 0; jp < JP; jp++) {
        float vlo[8], vhi[8];
#pragma unroll
        for (int p = 0; p < 8; p++) unpack2(acc[jp][p], vlo[p], vhi[p]);
#pragma unroll
        for (int h = 0; h < 2; h++) {
            int co = co_base + warp * CO_PW + jp * 2 + h;
            const float* src = h ? vhi : vlo;
            if (PARTIAL) {
                float* pp = g_part +
                            (((size_t)half * NB + b) * COUT + co) * H * W +
                            oy * W + tx0 + c0;
                float4 o0, o1;
                o0.x = src[0]; o0.y = src[1]; o0.z = src[2]; o0.w = src[3];
                o1.x = src[4]; o1.y = src[5]; o1.z = src[6]; o1.w = src[7];
                reinterpret_cast<float4*>(pp)[0] = o0;
                reinterpret_cast<float4*>(pp)[1] = o1;
            } else {
                float dm = demod[b * COUT + co];
                float bi = bias[co];
                float sn = styn[b * COUT + co];
                float* op = out + (size_t)b * COUT * H * W +
                            (size_t)co * H * W + oy * W + tx0 + c0;
                float4 o0, o1;
                float vv[8];
#pragma unroll
                for (int p = 0; p < 8; p++) {
                    float v = src[p] * dm + bi;
                    vv[p] = (v > 0.f ? v : 0.2f * v) * 1.41421356237309515f * sn;
                }
                o0.x = vv[0]; o0.y = vv[1]; o0.z = vv[2]; o0.w = vv[3];
                o1.x = vv[4]; o1.y = vv[5]; o1.z = vv[6]; o1.w = vv[7];
                reinterpret_cast<float4*>(op)[0] = o0;
                reinterpret_cast<float4*>(op)[1] = o1;
            }
        }
    }
}

// ---------------- l0 split-K combine: epilogue over summed partials ---------
// out(bufB)[b][co][hw] = leaky((p0+p1)*demod0 + bias) * sqrt2 * style1
__global__ void combine_l0_kernel(const float* __restrict__ bias) {
    int idx = blockIdx.x * blockDim.x + threadIdx.x;  // over 16*128*1024
    int b = idx >> 17;
    int co = (idx >> 10) & 127;
    float p = g_part[idx] + g_part[idx + 2097152];
    float v = p * g_demod0[b * 128 + co] + bias[co];
    v = (v > 0.f ? v : 0.2f * v) * 1.41421356237309515f * g_style1[b * 128 + co];
    g_bufB[idx] = v;
}

// ---------------- transposed conv (R9 winner, unchanged) --------------------
template <int CIN, int COUT, int HIN, bool SRC_A>
__global__ __launch_bounds__(256) void tconv_kernel(const float* __restrict__ wraw,
                                                    int demod_id) {
    constexpr int HOUT = 2 * HIN + 1;
    constexpr int CO_T = 32, CI_T = 8, TH = 8, TW = 32;
    constexpr int IR = 6, ICW = 18, IC_LD = 19;
    constexpr int W_LD = 34;
    constexpr int TILES_X = (HOUT + TW - 1) / TW;
    __shared__ __align__(16) float s_in[CI_T][IR][IC_LD];
    __shared__ __align__(16) float s_w[CI_T][9][W_LD];

    const float* in = SRC_A ? g_bufA : g_bufB;
    float* out = SRC_A ? g_bufB : g_bufA;
    const float* demod = demod_ptr(demod_id);

    int tid = threadIdx.x;
    int tile = blockIdx.x;
    int tx0 = (tile % TILES_X) * TW;
    int ty0 = (tile / TILES_X) * TH;
    int co_base = blockIdx.y * CO_T;
    int b = blockIdx.z;

    int co_grp = tid >> 6;
    int lane = tid & 31;
    int wrp = tid >> 5;
    int r = 2 * ((lane >> 3) & 3) + (wrp & 1);
    int c0 = (lane & 7) << 2;
    int h = c0 >> 1;

    int iy_base = (ty0 >> 1) - 1;
    int jx_base = (tx0 >> 1) - 1;

    ull acc[4][4];
#pragma unroll
    for (int jp = 0; jp < 4; jp++)
#pragma unroll
        for (int p = 0; p < 4; p++) acc[jp][p] = 0ull;

    const float wscale = rsqrtf((float)(CIN * 9));
    const float* in_b = in + (size_t)b * CIN * HIN * HIN;

    for (int cb = 0; cb < CIN; cb += CI_T) {
        __syncthreads();
        for (int idx = tid; idx < CI_T * IR * ICW; idx += 256) {
            int ci = idx / (IR * ICW);
            int rem = idx % (IR * ICW);
            int iy = rem / ICW, ix = rem % ICW;
            int gy = iy_base + iy, gx = jx_base + ix;
            float v = 0.f;
            if (gy >= 0 && gy < HIN && gx >= 0 && gx < HIN)
                v = in_b[(size_t)(cb + ci) * HIN * HIN + gy * HIN + gx];
            s_in[ci][iy][ix] = v;
        }
        for (int idx = tid; idx < CO_T * CI_T * 9; idx += 256) {
            int co = idx / (CI_T * 9);
            int rem = idx % (CI_T * 9);
            int ci = rem / 9, tap = rem % 9;
            s_w[ci][tap][co] =
                wraw[((size_t)(co_base + co) * CIN + cb + ci) * 9 + tap] * wscale;
        }
        __syncthreads();
#pragma unroll
        for (int ci = 0; ci < CI_T; ci++) {
            int ky0 = r & 1;
            for (int ky = ky0; ky < 3; ky += 2) {
                int ir = ((r + ky - 2) >> 1) + 1;
                float x0v = s_in[ci][ir][h];
                float x1v = s_in[ci][ir][h + 1];
                float x2v = s_in[ci][ir][h + 2];
                ull xd0 = pack2(x0v, x0v);
                ull xd1 = pack2(x1v, x1v);
                ull xd2 = pack2(x2v, x2v);
                int wr = (2 - ky) * 3;
#pragma unroll
                for (int jp = 0; jp < 4; jp++) {
                    int co = co_grp * 8 + jp * 2;
                    ull w0 = *reinterpret_cast<const ull*>(&s_w[ci][wr + 0][co]);
                    ull w1 = *reinterpret_cast<const ull*>(&s_w[ci][wr + 1][co]);
                    ull w2 = *reinterpret_cast<const ull*>(&s_w[ci][wr + 2][co]);
                    ffma2(acc[jp][0], w2, xd0);
                    ffma2(acc[jp][0], w0, xd1);
                    ffma2(acc[jp][1], w1, xd1);
                    ffma2(acc[jp][2], w2, xd1);
                    ffma2(acc[jp][2], w0, xd2);
                    ffma2(acc[jp][3], w1, xd2);
                }
            }
        }
    }
    int oy = ty0 + r;
    if (oy >= HOUT) return;
    float* out_b = out + (size_t)b * COUT * HOUT * HOUT;
#pragma unroll
    for (int jp = 0; jp < 4; jp++) {
#pragma unroll
        for (int hh = 0; hh < 2; hh++) {
            int co = co_base + co_grp * 8 + jp * 2 + hh;
            float dm = demod[b * COUT + co];
#pragma unroll
            for (int p = 0; p < 4; p++) {
                float lo, hi;
                unpack2(acc[jp][p], lo, hi);
                float v = (hh ? hi : lo) * dm;
                int ox = tx0 + c0 + p;
                if (ox < HOUT)
                    out_b[(size_t)co * HOUT * HOUT + oy * HOUT + ox] = v;
            }
        }
    }
}

// ---------------- 4x4 blur + bias + leaky*sqrt2*style_next ----------------
template <int C, int HIN, bool SRC_A>
__global__ __launch_bounds__(256) void blur_kernel(const float* __restrict__ bias,
                                                   int style_id) {
    constexpr int HOUT = HIN - 1;
    constexpr int TH = 16, TW = 32;
    constexpr int TILES_X = HOUT / TW;
    __shared__ float s[TH + 3][TW + 4];

    const float* in = SRC_A ? g_bufA : g_bufB;
    float* out = SRC_A ? g_bufB : g_bufA;

    int tile = blockIdx.x;
    int x0 = (tile % TILES_X) * TW;
    int y0 = (tile / TILES_X) * TH;
    int c = blockIdx.y, b = blockIdx.z;
    const float* ip = in + ((size_t)b * C + c) * HIN * HIN;

    for (int idx = threadIdx.x; idx < (TH + 3) * (TW + 3); idx += 256) {
        int iy = idx / (TW + 3), ix = idx % (TW + 3);
        int gy = y0 + iy - 1, gx = x0 + ix - 1;
        float v = 0.f;
        if (gy >= 0 && gy < HIN && gx >= 0 && gx < HIN) v = ip[gy * HIN + gx];
        s[iy][ix] = v;
    }
    __syncthreads();

    const float c4[4] = {0.25f, 0.75f, 0.75f, 0.25f};
    float bi = bias[c];
    float sn = style_ptr(style_id)[b * C + c];
    float* op = out + ((size_t)b * C + c) * HOUT * HOUT;
#pragma unroll
    for (int q = 0; q < 2; q++) {
        int px = threadIdx.x + q * 256;
        int ly = px >> 5, lx = px & 31;
        float a = 0.f;
#pragma unroll
        for (int ky = 0; ky < 4; ky++) {
            float rs = 0.f;
#pragma unroll
            for (int kx = 0; kx < 4; kx++) rs += c4[kx] * s[ly + ky][lx + kx];
            a += c4[ky] * rs;
        }
        a += bi;
        a = (a > 0.f ? a : 0.2f * a) * 1.41421356237309515f * sn;
        op[(y0 + ly) * HOUT + x0 + lx] = a;
    }
}

// ---------------- final 1x1 (32 -> 3 of 4 ch), + out_bias ----------------
__global__ void final_kernel(const float* __restrict__ finw,
                             const float* __restrict__ outb,
                             float* __restrict__ out) {
    int idx = blockIdx.x * blockDim.x + threadIdx.x;
    int b = idx >> 14;
    int p = idx & 16383;
    const float* ib = g_bufB + (size_t)b * 32 * 16384 + p;
    float a0 = 0.f, a1 = 0.f, a2 = 0.f;
#pragma unroll
    for (int ci = 0; ci < 32; ci++) {
        float v = ib[(size_t)ci * 16384];
        a0 = fmaf(finw[ci], v, a0);
        a1 = fmaf(finw[32 + ci], v, a1);
        a2 = fmaf(finw[64 + ci], v, a2);
    }
    const float sc = rsqrtf(32.0f);
    out[(size_t)b * 3 * 16384 + p] = a0 * sc + outb[0];
    out[(size_t)b * 3 * 16384 + 16384 + p] = a1 * sc + outb[1];
    out[(size_t)b * 3 * 16384 + 2 * 16384 + p] = a2 * sc + outb[2];
}

// ------------------------------------------------------------------------
extern "C" void kernel_launch(void* const* d_in, const int* in_sizes, int n_in,
                              void* d_out, int out_size) {
    (void)in_sizes; (void)n_in; (void)out_size;
    const float* fg = (const float*)d_in[0];
    const float* mask = (const float*)d_in[1];
    const float* bg = (const float*)d_in[2];
    const float* z = (const float*)d_in[3];
    const float* l_w[5]  = {(const float*)d_in[4],  (const float*)d_in[8],
                            (const float*)d_in[12], (const float*)d_in[16],
                            (const float*)d_in[20]};
    const float* l_mw[5] = {(const float*)d_in[5],  (const float*)d_in[9],
                            (const float*)d_in[13], (const float*)d_in[17],
                            (const float*)d_in[21]};
    const float* l_mb[5] = {(const float*)d_in[6],  (const float*)d_in[10],
                            (const float*)d_in[14], (const float*)d_in[18],
                            (const float*)d_in[22]};
    const float* l_b[5]  = {(const float*)d_in[7],  (const float*)d_in[11],
                            (const float*)d_in[15], (const float*)d_in[19],
                            (const float*)d_in[23]};
    const float* finw = (const float*)d_in[24];
    const float* fin_mw = (const float*)d_in[25];
    const float* fin_mb = (const float*)d_in[26];
    const float* outb = (const float*)d_in[27];

    // fused setup: 2 kernels
    P6 mw6, mb6;
    for (int l = 0; l < 5; l++) { mw6.a[l] = l_mw[l]; mb6.a[l] = l_mb[l]; }
    mw6.a[5] = fin_mw; mb6.a[5] = fin_mb;
    style_all_kernel<<<1344, 256>>>(z, mw6, mb6);
    P5 w5;
    for (int l = 0; l < 5; l++) w5.a[l] = l_w[l];
    demod_all_kernel<<<832, 256>>>(w5);

    // compose + modulate for layer 0 -> bufA
    compose_kernel<<<(NB * 256 * 1024) / 256, 256>>>(fg, mask, bg);

    // l0: 256->128 @32x32, split-K=2, CO_T=32 -> 512 CTAs, partials -> g_part
    conv3x3_kernel<256, 128, 128, 32, 32, true, 32, true>
        <<<dim3(4, 4, 32), 256>>>(l_w[0], l_b[0], 0, 1);
    combine_l0_kernel<<<8192, 256>>>(l_b[0]);
    // l1: tconv 128->128, 32 -> 65   (B -> A)
    tconv_kernel<128, 128, 32, false><<<dim3(27, 4, NB), 256>>>(l_w[1], 1);
    // blur 65 -> 64 + act + style2   (A -> B)
    blur_kernel<128, 65, true><<<dim3(8, 128, NB), 256>>>(l_b[1], 2);
    // l2: 128->64 @64x64   (B -> A)
    conv3x3_kernel<128, 128, 64, 64, 64, false, 32, false>
        <<<dim3(16, 2, NB), 256>>>(l_w[2], l_b[2], 2, 3);
    // l3: tconv 64->64, 64 -> 129   (A -> B)
    tconv_kernel<64, 64, 64, true><<<dim3(85, 2, NB), 256>>>(l_w[3], 3);
    // blur 129 -> 128 + act + style4   (B -> A)
    blur_kernel<64, 129, false><<<dim3(32, 64, NB), 256>>>(l_b[3], 4);
    // l4: 64->32 @128x128   (A -> B)
    conv3x3_kernel<64, 64, 32, 128, 128, true, 32, false>
        <<<dim3(64, 1, NB), 256>>>(l_w[4], l_b[4], 4, 5);
    // final 1x1 32->3 + out_bias   (B -> d_out)
    final_kernel<<<(NB * 16384) / 256, 256>>>(finw, outb, (float*)d_out);
}

// round 11
// speedup vs baseline: 1.3683x; 1.1222x over previous
#include <cuda_runtime.h>
#include <math.h>

#define NB 16
#define SDIM 512

typedef unsigned long long ull;

__device__ __forceinline__ ull pack2(float a, float b) {
    ull r;
    asm("mov.b64 %0, {%1, %2};" : "=l"(r) : "f"(a), "f"(b));
    return r;
}
__device__ __forceinline__ void unpack2(ull v, float& a, float& b) {
    asm("mov.b64 {%0, %1}, %2;" : "=f"(a), "=f"(b) : "l"(v));
}
__device__ __forceinline__ void ffma2(ull& d, ull a, ull b) {
    asm("fma.rn.f32x2 %0, %1, %2, %0;" : "+l"(d) : "l"(a), "l"(b));
}

// ---------------- persistent scratch (no allocs allowed) ----------------
static __device__ float g_bufA[16777216];   // max: (16,64,128,128)
static __device__ float g_bufB[17040384];   // max: (16,64,129,129)
static __device__ float g_part[8388608];    // split-K partials (l0: 4 halves, l2: 2)

static __device__ float g_style0[NB * 256];
static __device__ float g_style1[NB * 128];
static __device__ float g_style2[NB * 128];
static __device__ float g_style3[NB * 64];
static __device__ float g_style4[NB * 64];
static __device__ float g_stylef[NB * 32];

static __device__ float g_demod0[NB * 128];
static __device__ float g_demod1[NB * 128];
static __device__ float g_demod2[NB * 64];
static __device__ float g_demod3[NB * 64];
static __device__ float g_demod4[NB * 32];

__device__ __forceinline__ float* style_ptr(int id) {
    switch (id) {
        case 0: return g_style0;
        case 1: return g_style1;
        case 2: return g_style2;
        case 3: return g_style3;
        case 4: return g_style4;
        default: return g_stylef;
    }
}
__device__ __forceinline__ float* demod_ptr(int id) {
    switch (id) {
        case 0: return g_demod0;
        case 1: return g_demod1;
        case 2: return g_demod2;
        case 3: return g_demod3;
        default: return g_demod4;
    }
}

struct P6 { const float* a[6]; };
struct P5 { const float* a[5]; };

// ---------------- fused style kernel: all 6 layers ----------------
__global__ void style_all_kernel(const float* __restrict__ z, P6 mw, P6 mb) {
    int gw = blockIdx.x * 8 + (threadIdx.x >> 5);
    int lane = threadIdx.x & 31;
    if (gw >= NB * 672) return;
    int b = gw / 672;
    int c = gw - b * 672;
    int L, ci, Ci;
    if (c < 256)      { L = 0; ci = c;       Ci = 256; }
    else if (c < 384) { L = 1; ci = c - 256; Ci = 128; }
    else if (c < 512) { L = 2; ci = c - 384; Ci = 128; }
    else if (c < 576) { L = 3; ci = c - 512; Ci = 64; }
    else if (c < 640) { L = 4; ci = c - 576; Ci = 64; }
    else              { L = 5; ci = c - 640; Ci = 32; }
    const float* zr = z + b * SDIM;
    const float* mr = mw.a[L] + (size_t)ci * SDIM;
    float s = 0.f;
#pragma unroll 4
    for (int k = lane; k < SDIM; k += 32) s += zr[k] * mr[k];
#pragma unroll
    for (int o = 16; o; o >>= 1) s += __shfl_xor_sync(0xffffffffu, s, o);
    if (lane == 0)
        style_ptr(L)[b * Ci + ci] = s * 0.04419417382415922f + mb.a[L][ci];
}

// ---------------- fused demod kernel, wsq inline ----------------
__global__ void demod_all_kernel(P5 w) {
    int gw = blockIdx.x * 8 + (threadIdx.x >> 5);
    int lane = threadIdx.x & 31;
    if (gw >= NB * 416) return;
    int b = gw / 416;
    int c = gw - b * 416;
    int L, co, Co, Ci;
    if (c < 128)      { L = 0; co = c;       Co = 128; Ci = 256; }
    else if (c < 256) { L = 1; co = c - 128; Co = 128; Ci = 128; }
    else if (c < 320) { L = 2; co = c - 256; Co = 64;  Ci = 128; }
    else if (c < 384) { L = 3; co = c - 320; Co = 64;  Ci = 64; }
    else              { L = 4; co = c - 384; Co = 32;  Ci = 64; }
    const float* st = style_ptr(L) + b * Ci;
    const float* wb = w.a[L] + (size_t)co * Ci * 9;
    float s = 0.f;
    for (int ci = lane; ci < Ci; ci += 32) {
        const float* p = wb + ci * 9;
        float wq = 0.f;
#pragma unroll
        for (int t = 0; t < 9; t++) wq += p[t] * p[t];
        float sv = st[ci];
        s += sv * sv * wq;
    }
#pragma unroll
    for (int o = 16; o; o >>= 1) s += __shfl_xor_sync(0xffffffffu, s, o);
    if (lane == 0)
        demod_ptr(L)[b * Co + co] = rsqrtf(s * (1.0f / (float)(Ci * 9)) + 1e-8f);
}

// ---------------- compose: bufA = (fg + (1-mask)*bg) * style0 ----------------
__global__ void compose_kernel(const float* __restrict__ fg,
                               const float* __restrict__ mask,
                               const float* __restrict__ bg) {
    int idx = blockIdx.x * blockDim.x + threadIdx.x;
    int p = idx & 1023;
    int c = (idx >> 10) & 255;
    int b = idx >> 18;
    float m = 1.0f - mask[b * 1024 + p];
    float v = fg[idx] + m * bg[idx];
    g_bufA[idx] = v * g_style0[b * 256 + c];
}

// ---------------- 3x3 conv, pad 1, f32x2; shift/mask staging; split-K -------
// Input smem layout [iy][ci][col]: interior staging uses only shifts/masks.
// NSPLIT>1: raw partials to g_part[half][b][co][hw]; else styled epilogue.
template <int CIN_TOT, int CIN_DO, int COUT, int H, int W, bool SRC_A, int CO_T,
          int NSPLIT>
__global__ __launch_bounds__(256) void conv3x3_kernel(const float* __restrict__ wraw,
                                                      const float* __restrict__ bias,
                                                      int demod_id, int style_id) {
    constexpr int CI_T = 8, TH = 8, TW = 32;
    constexpr int CO_PW = CO_T / 8;
    constexpr int JP = CO_PW / 2;
    constexpr int IN_LD = 36;
    constexpr int W_LD = CO_T + 2;
    constexpr int TILES_X = W / TW;
    // [iy][ci(+1 pad)][col]: ci-stride 36 (≡4 mod 32 per iy via 9*36), keeps
    // LDS.128 reads conflict-free per phase and float4-aligned.
    __shared__ __align__(16) float s_in[TH + 2][CI_T + 1][IN_LD];
    __shared__ __align__(16) float s_w[CI_T][9][W_LD];

    const float* in = SRC_A ? g_bufA : g_bufB;
    float* out = SRC_A ? g_bufB : g_bufA;
    const float* demod = demod_ptr(demod_id);
    const float* styn = style_ptr(style_id);

    int tid = threadIdx.x;
    int tile = blockIdx.x;
    int tx0 = (tile % TILES_X) * TW;
    int ty0 = (tile / TILES_X) * TH;
    int co_base = blockIdx.y * CO_T;

    int b = blockIdx.z / NSPLIT;
    int half = blockIdx.z % NSPLIT;
    int cin_off = half * CIN_DO;

    int warp = tid >> 5;
    int lane = tid & 31;
    int r = lane >> 2;
    int c0 = (lane & 3) << 3;

    ull acc[JP][8];
#pragma unroll
    for (int jp = 0; jp < JP; jp++)
#pragma unroll
        for (int p = 0; p < 8; p++) acc[jp][p] = 0ull;

    const float wscale = rsqrtf((float)(CIN_TOT * 9));
    const float* in_b = in + (size_t)b * CIN_TOT * H * W;

    // shift/mask pieces for interior staging (stage-invariant)
    int colA = tid & 31;                 // col 0..31 per iter
    int gxA = tx0 + colA - 1;
    bool gxA_ok = (gxA >= 0 && gxA < W);
    // halo columns (ix 32,33), 160 threads
    int ixB = 32 + (tid & 1);
    int rowB = tid >> 1;                 // 0..79
    int iyB = rowB >> 3, ciB = rowB & 7;
    int gxB = tx0 + ixB - 1;
    int gyB = ty0 + iyB - 1;
    bool B_ok = (tid < 160) && gxB >= 0 && gxB < W && gyB >= 0 && gyB < H;

    for (int cb = 0; cb < CIN_DO; cb += CI_T) {
        __syncthreads();
        const float* in_c = in_b + (size_t)(cin_off + cb) * H * W;
        // interior: 10 iters, pure shift/mask indexing
#pragma unroll
        for (int k = 0; k < 10; k++) {
            int rowq = (tid + k * 256) >> 5;     // 0..79
            int iy = rowq >> 3;
            int ci = rowq & 7;
            int gy = ty0 + iy - 1;
            float v = 0.f;
            if (gy >= 0 && gy < H && gxA_ok)
                v = in_c[ci * H * W + gy * W + gxA];
            s_in[iy][ci][colA] = v;
        }
        // halo columns
        {
            float v = 0.f;
            if (B_ok) v = in_c[ciB * H * W + gyB * W + gxB];
            if (tid < 160) s_in[iyB][ciB][ixB] = v;
        }
        // weights (layout/indexing unchanged from R10 winner)
#pragma unroll
        for (int k = 0; k < 9; k++) {
            int idx = tid + k * 256;
            int co = idx / (CI_T * 9);
            int rem = idx % (CI_T * 9);
            int ci = rem / 9, tap = rem % 9;
            s_w[ci][tap][co] =
                wraw[((size_t)(co_base + co) * CIN_TOT + cin_off + cb + ci) * 9 +
                     tap] * wscale;
        }
        __syncthreads();
#pragma unroll
        for (int ci = 0; ci < CI_T; ci++) {
#pragma unroll
            for (int ky = 0; ky < 3; ky++) {
                const float4* row4 =
                    reinterpret_cast<const float4*>(&s_in[r + ky][ci][c0]);
                float4 q0 = row4[0];
                float4 q1 = row4[1];
                float4 q2 = row4[2];
                ull xd[10];
                xd[0] = pack2(q0.x, q0.x); xd[1] = pack2(q0.y, q0.y);
                xd[2] = pack2(q0.z, q0.z); xd[3] = pack2(q0.w, q0.w);
                xd[4] = pack2(q1.x, q1.x); xd[5] = pack2(q1.y, q1.y);
                xd[6] = pack2(q1.z, q1.z); xd[7] = pack2(q1.w, q1.w);
                xd[8] = pack2(q2.x, q2.x); xd[9] = pack2(q2.y, q2.y);
#pragma unroll
                for (int kx = 0; kx < 3; kx++) {
#pragma unroll
                    for (int jp = 0; jp < JP; jp++) {
                        ull w2 = *reinterpret_cast<const ull*>(
                            &s_w[ci][ky * 3 + kx][warp * CO_PW + jp * 2]);
#pragma unroll
                        for (int p = 0; p < 8; p++) ffma2(acc[jp][p], w2, xd[kx + p]);
                    }
                }
            }
        }
    }
    int oy = ty0 + r;
#pragma unroll
    for (int jp = 0; jp < JP; jp++) {
        float vlo[8], vhi[8];
#pragma unroll
        for (int p = 0; p < 8; p++) unpack2(acc[jp][p], vlo[p], vhi[p]);
#pragma unroll
        for (int h = 0; h < 2; h++) {
            int co = co_base + warp * CO_PW + jp * 2 + h;
            const float* src = h ? vhi : vlo;
            if (NSPLIT > 1) {
                float* pp = g_part +
                            (((size_t)half * NB + b) * COUT + co) * H * W +
                            oy * W + tx0 + c0;
                float4 o0, o1;
                o0.x = src[0]; o0.y = src[1]; o0.z = src[2]; o0.w = src[3];
                o1.x = src[4]; o1.y = src[5]; o1.z = src[6]; o1.w = src[7];
                reinterpret_cast<float4*>(pp)[0] = o0;
                reinterpret_cast<float4*>(pp)[1] = o1;
            } else {
                float dm = demod[b * COUT + co];
                float bi = bias[co];
                float sn = styn[b * COUT + co];
                float* op = out + (size_t)b * COUT * H * W +
                            (size_t)co * H * W + oy * W + tx0 + c0;
                float4 o0, o1;
                float vv[8];
#pragma unroll
                for (int p = 0; p < 8; p++) {
                    float v = src[p] * dm + bi;
                    vv[p] = (v > 0.f ? v : 0.2f * v) * 1.41421356237309515f * sn;
                }
                o0.x = vv[0]; o0.y = vv[1]; o0.z = vv[2]; o0.w = vv[3];
                o1.x = vv[4]; o1.y = vv[5]; o1.z = vv[6]; o1.w = vv[7];
                reinterpret_cast<float4*>(op)[0] = o0;
                reinterpret_cast<float4*>(op)[1] = o1;
            }
        }
    }
}

// ---------------- split-K combine: sum partials + styled epilogue -----------
// CO*HW and HW are powers of 2. DST_B: write bufB else bufA.
template <int CO, int HW, int NHALF, bool DST_B>
__global__ void combine_kernel(const float* __restrict__ bias,
                               int demod_id, int style_id) {
    int idx = blockIdx.x * blockDim.x + threadIdx.x;   // over NB*CO*HW
    constexpr int COHW = CO * HW;
    int b = idx / COHW;            // COHW pow2 -> shift
    int co = (idx / HW) & (CO - 1);
    float p = 0.f;
#pragma unroll
    for (int h = 0; h < NHALF; h++) p += g_part[idx + (size_t)h * NB * COHW];
    float v = p * demod_ptr(demod_id)[b * CO + co] + bias[co];
    v = (v > 0.f ? v : 0.2f * v) * 1.41421356237309515f *
        style_ptr(style_id)[b * CO + co];
    (DST_B ? g_bufB : g_bufA)[idx] = v;
}

// ---------------- transposed conv (R9/R10 winner, unchanged) ----------------
template <int CIN, int COUT, int HIN, bool SRC_A>
__global__ __launch_bounds__(256) void tconv_kernel(const float* __restrict__ wraw,
                                                    int demod_id) {
    constexpr int HOUT = 2 * HIN + 1;
    constexpr int CO_T = 32, CI_T = 8, TH = 8, TW = 32;
    constexpr int IR = 6, ICW = 18, IC_LD = 19;
    constexpr int W_LD = 34;
    constexpr int TILES_X = (HOUT + TW - 1) / TW;
    __shared__ __align__(16) float s_in[CI_T][IR][IC_LD];
    __shared__ __align__(16) float s_w[CI_T][9][W_LD];

    const float* in = SRC_A ? g_bufA : g_bufB;
    float* out = SRC_A ? g_bufB : g_bufA;
    const float* demod = demod_ptr(demod_id);

    int tid = threadIdx.x;
    int tile = blockIdx.x;
    int tx0 = (tile % TILES_X) * TW;
    int ty0 = (tile / TILES_X) * TH;
    int co_base = blockIdx.y * CO_T;
    int b = blockIdx.z;

    int co_grp = tid >> 6;
    int lane = tid & 31;
    int wrp = tid >> 5;
    int r = 2 * ((lane >> 3) & 3) + (wrp & 1);
    int c0 = (lane & 7) << 2;
    int h = c0 >> 1;

    int iy_base = (ty0 >> 1) - 1;
    int jx_base = (tx0 >> 1) - 1;

    ull acc[4][4];
#pragma unroll
    for (int jp = 0; jp < 4; jp++)
#pragma unroll
        for (int p = 0; p < 4; p++) acc[jp][p] = 0ull;

    const float wscale = rsqrtf((float)(CIN * 9));
    const float* in_b = in + (size_t)b * CIN * HIN * HIN;

    for (int cb = 0; cb < CIN; cb += CI_T) {
        __syncthreads();
        for (int idx = tid; idx < CI_T * IR * ICW; idx += 256) {
            int ci = idx / (IR * ICW);
            int rem = idx % (IR * ICW);
            int iy = rem / ICW, ix = rem % ICW;
            int gy = iy_base + iy, gx = jx_base + ix;
            float v = 0.f;
            if (gy >= 0 && gy < HIN && gx >= 0 && gx < HIN)
                v = in_b[(size_t)(cb + ci) * HIN * HIN + gy * HIN + gx];
            s_in[ci][iy][ix] = v;
        }
        for (int idx = tid; idx < CO_T * CI_T * 9; idx += 256) {
            int co = idx / (CI_T * 9);
            int rem = idx % (CI_T * 9);
            int ci = rem / 9, tap = rem % 9;
            s_w[ci][tap][co] =
                wraw[((size_t)(co_base + co) * CIN + cb + ci) * 9 + tap] * wscale;
        }
        __syncthreads();
#pragma unroll
        for (int ci = 0; ci < CI_T; ci++) {
            int ky0 = r & 1;
            for (int ky = ky0; ky < 3; ky += 2) {
                int ir = ((r + ky - 2) >> 1) + 1;
                float x0v = s_in[ci][ir][h];
                float x1v = s_in[ci][ir][h + 1];
                float x2v = s_in[ci][ir][h + 2];
                ull xd0 = pack2(x0v, x0v);
                ull xd1 = pack2(x1v, x1v);
                ull xd2 = pack2(x2v, x2v);
                int wr = (2 - ky) * 3;
#pragma unroll
                for (int jp = 0; jp < 4; jp++) {
                    int co = co_grp * 8 + jp * 2;
                    ull w0 = *reinterpret_cast<const ull*>(&s_w[ci][wr + 0][co]);
                    ull w1 = *reinterpret_cast<const ull*>(&s_w[ci][wr + 1][co]);
                    ull w2 = *reinterpret_cast<const ull*>(&s_w[ci][wr + 2][co]);
                    ffma2(acc[jp][0], w2, xd0);
                    ffma2(acc[jp][0], w0, xd1);
                    ffma2(acc[jp][1], w1, xd1);
                    ffma2(acc[jp][2], w2, xd1);
                    ffma2(acc[jp][2], w0, xd2);
                    ffma2(acc[jp][3], w1, xd2);
                }
            }
        }
    }
    int oy = ty0 + r;
    if (oy >= HOUT) return;
    float* out_b = out + (size_t)b * COUT * HOUT * HOUT;
#pragma unroll
    for (int jp = 0; jp < 4; jp++) {
#pragma unroll
        for (int hh = 0; hh < 2; hh++) {
            int co = co_base + co_grp * 8 + jp * 2 + hh;
            float dm = demod[b * COUT + co];
#pragma unroll
            for (int p = 0; p < 4; p++) {
                float lo, hi;
                unpack2(acc[jp][p], lo, hi);
                float v = (hh ? hi : lo) * dm;
                int ox = tx0 + c0 + p;
                if (ox < HOUT)
                    out_b[(size_t)co * HOUT * HOUT + oy * HOUT + ox] = v;
            }
        }
    }
}

// ---------------- 4x4 blur + bias + leaky*sqrt2*style_next ----------------
template <int C, int HIN, bool SRC_A>
__global__ __launch_bounds__(256) void blur_kernel(const float* __restrict__ bias,
                                                   int style_id) {
    constexpr int HOUT = HIN - 1;
    constexpr int TH = 16, TW = 32;
    constexpr int TILES_X = HOUT / TW;
    __shared__ float s[TH + 3][TW + 4];

    const float* in = SRC_A ? g_bufA : g_bufB;
    float* out = SRC_A ? g_bufB : g_bufA;

    int tile = blockIdx.x;
    int x0 = (tile % TILES_X) * TW;
    int y0 = (tile / TILES_X) * TH;
    int c = blockIdx.y, b = blockIdx.z;
    const float* ip = in + ((size_t)b * C + c) * HIN * HIN;

    for (int idx = threadIdx.x; idx < (TH + 3) * (TW + 3); idx += 256) {
        int iy = idx / (TW + 3), ix = idx % (TW + 3);
        int gy = y0 + iy - 1, gx = x0 + ix - 1;
        float v = 0.f;
        if (gy >= 0 && gy < HIN && gx >= 0 && gx < HIN) v = ip[gy * HIN + gx];
        s[iy][ix] = v;
    }
    __syncthreads();

    const float c4[4] = {0.25f, 0.75f, 0.75f, 0.25f};
    float bi = bias[c];
    float sn = style_ptr(style_id)[b * C + c];
    float* op = out + ((size_t)b * C + c) * HOUT * HOUT;
#pragma unroll
    for (int q = 0; q < 2; q++) {
        int px = threadIdx.x + q * 256;
        int ly = px >> 5, lx = px & 31;
        float a = 0.f;
#pragma unroll
        for (int ky = 0; ky < 4; ky++) {
            float rs = 0.f;
#pragma unroll
            for (int kx = 0; kx < 4; kx++) rs += c4[kx] * s[ly + ky][lx + kx];
            a += c4[ky] * rs;
        }
        a += bi;
        a = (a > 0.f ? a : 0.2f * a) * 1.41421356237309515f * sn;
        op[(y0 + ly) * HOUT + x0 + lx] = a;
    }
}

// ---------------- final 1x1 (32 -> 3 of 4 ch), + out_bias ----------------
__global__ void final_kernel(const float* __restrict__ finw,
                             const float* __restrict__ outb,
                             float* __restrict__ out) {
    int idx = blockIdx.x * blockDim.x + threadIdx.x;
    int b = idx >> 14;
    int p = idx & 16383;
    const float* ib = g_bufB + (size_t)b * 32 * 16384 + p;
    float a0 = 0.f, a1 = 0.f, a2 = 0.f;
#pragma unroll
    for (int ci = 0; ci < 32; ci++) {
        float v = ib[(size_t)ci * 16384];
        a0 = fmaf(finw[ci], v, a0);
        a1 = fmaf(finw[32 + ci], v, a1);
        a2 = fmaf(finw[64 + ci], v, a2);
    }
    const float sc = rsqrtf(32.0f);
    out[(size_t)b * 3 * 16384 + p] = a0 * sc + outb[0];
    out[(size_t)b * 3 * 16384 + 16384 + p] = a1 * sc + outb[1];
    out[(size_t)b * 3 * 16384 + 2 * 16384 + p] = a2 * sc + outb[2];
}

// ------------------------------------------------------------------------
extern "C" void kernel_launch(void* const* d_in, const int* in_sizes, int n_in,
                              void* d_out, int out_size) {
    (void)in_sizes; (void)n_in; (void)out_size;
    const float* fg = (const float*)d_in[0];
    const float* mask = (const float*)d_in[1];
    const float* bg = (const float*)d_in[2];
    const float* z = (const float*)d_in[3];
    const float* l_w[5]  = {(const float*)d_in[4],  (const float*)d_in[8],
                            (const float*)d_in[12], (const float*)d_in[16],
                            (const float*)d_in[20]};
    const float* l_mw[5] = {(const float*)d_in[5],  (const float*)d_in[9],
                            (const float*)d_in[13], (const float*)d_in[17],
                            (const float*)d_in[21]};
    const float* l_mb[5] = {(const float*)d_in[6],  (const float*)d_in[10],
                            (const float*)d_in[14], (const float*)d_in[18],
                            (const float*)d_in[22]};
    const float* l_b[5]  = {(const float*)d_in[7],  (const float*)d_in[11],
                            (const float*)d_in[15], (const float*)d_in[19],
                            (const float*)d_in[23]};
    const float* finw = (const float*)d_in[24];
    const float* fin_mw = (const float*)d_in[25];
    const float* fin_mb = (const float*)d_in[26];
    const float* outb = (const float*)d_in[27];

    // fused setup: 2 kernels
    P6 mw6, mb6;
    for (int l = 0; l < 5; l++) { mw6.a[l] = l_mw[l]; mb6.a[l] = l_mb[l]; }
    mw6.a[5] = fin_mw; mb6.a[5] = fin_mb;
    style_all_kernel<<<1344, 256>>>(z, mw6, mb6);
    P5 w5;
    for (int l = 0; l < 5; l++) w5.a[l] = l_w[l];
    demod_all_kernel<<<832, 256>>>(w5);

    // compose + modulate for layer 0 -> bufA
    compose_kernel<<<(NB * 256 * 1024) / 256, 256>>>(fg, mask, bg);

    // l0: 256->128 @32x32, split-K=4 -> 1024 CTAs, partials -> g_part
    conv3x3_kernel<256, 64, 128, 32, 32, true, 32, 4>
        <<<dim3(4, 4, 64), 256>>>(l_w[0], l_b[0], 0, 1);
    combine_kernel<128, 1024, 4, true><<<8192, 256>>>(l_b[0], 0, 1);
    // l1: tconv 128->128, 32 -> 65   (B -> A)
    tconv_kernel<128, 128, 32, false><<<dim3(27, 4, NB), 256>>>(l_w[1], 1);
    // blur 65 -> 64 + act + style2   (A -> B)
    blur_kernel<128, 65, true><<<dim3(8, 128, NB), 256>>>(l_b[1], 2);
    // l2: 128->64 @64x64, split-K=2 -> 1024 CTAs, partials -> g_part
    conv3x3_kernel<128, 64, 64, 64, 64, false, 32, 2>
        <<<dim3(16, 2, 32), 256>>>(l_w[2], l_b[2], 2, 3);
    combine_kernel<64, 4096, 2, false><<<16384, 256>>>(l_b[2], 2, 3);
    // l3: tconv 64->64, 64 -> 129   (A -> B)
    tconv_kernel<64, 64, 64, true><<<dim3(85, 2, NB), 256>>>(l_w[3], 3);
    // blur 129 -> 128 + act + style4   (B -> A)
    blur_kernel<64, 129, false><<<dim3(32, 64, NB), 256>>>(l_b[3], 4);
    // l4: 64->32 @128x128   (A -> B)
    conv3x3_kernel<64, 64, 32, 128, 128, true, 32, 1>
        <<<dim3(64, 1, 16), 256>>>(l_w[4], l_b[4], 4, 5);
    // final 1x1 32->3 + out_bias   (B -> d_out)
    final_kernel<<<(NB * 16384) / 256, 256>>>(finw, outb, (float*)d_out);
}

// round 12
// speedup vs baseline: 1.5046x; 1.0996x over previous
#include <cuda_runtime.h>
#include <math.h>

#define NB 16
#define SDIM 512

typedef unsigned long long ull;

__device__ __forceinline__ ull pack2(float a, float b) {
    ull r;
    asm("mov.b64 %0, {%1, %2};" : "=l"(r) : "f"(a), "f"(b));
    return r;
}
__device__ __forceinline__ void unpack2(ull v, float& a, float& b) {
    asm("mov.b64 {%0, %1}, %2;" : "=f"(a), "=f"(b) : "l"(v));
}
__device__ __forceinline__ void ffma2(ull& d, ull a, ull b) {
    asm("fma.rn.f32x2 %0, %1, %2, %0;" : "+l"(d) : "l"(a), "l"(b));
}

// ---------------- persistent scratch (no allocs allowed) ----------------
static __device__ float g_bufA[16777216];   // max: (16,64,128,128)
static __device__ float g_bufB[17040384];   // max: (16,64,129,129)
static __device__ float g_part[8388608];    // split-K partials

static __device__ float g_style0[NB * 256];
static __device__ float g_style1[NB * 128];
static __device__ float g_style2[NB * 128];
static __device__ float g_style3[NB * 64];
static __device__ float g_style4[NB * 64];
static __device__ float g_stylef[NB * 32];

static __device__ float g_demod0[NB * 128];
static __device__ float g_demod1[NB * 128];
static __device__ float g_demod2[NB * 64];
static __device__ float g_demod3[NB * 64];
static __device__ float g_demod4[NB * 32];

__device__ __forceinline__ float* style_ptr(int id) {
    switch (id) {
        case 0: return g_style0;
        case 1: return g_style1;
        case 2: return g_style2;
        case 3: return g_style3;
        case 4: return g_style4;
        default: return g_stylef;
    }
}
__device__ __forceinline__ float* demod_ptr(int id) {
    switch (id) {
        case 0: return g_demod0;
        case 1: return g_demod1;
        case 2: return g_demod2;
        case 3: return g_demod3;
        default: return g_demod4;
    }
}

struct P6 { const float* a[6]; };
struct P5 { const float* a[5]; };

// ---------------- fused style kernel: all 6 layers ----------------
__global__ void style_all_kernel(const float* __restrict__ z, P6 mw, P6 mb) {
    int gw = blockIdx.x * 8 + (threadIdx.x >> 5);
    int lane = threadIdx.x & 31;
    if (gw >= NB * 672) return;
    int b = gw / 672;
    int c = gw - b * 672;
    int L, ci, Ci;
    if (c < 256)      { L = 0; ci = c;       Ci = 256; }
    else if (c < 384) { L = 1; ci = c - 256; Ci = 128; }
    else if (c < 512) { L = 2; ci = c - 384; Ci = 128; }
    else if (c < 576) { L = 3; ci = c - 512; Ci = 64; }
    else if (c < 640) { L = 4; ci = c - 576; Ci = 64; }
    else              { L = 5; ci = c - 640; Ci = 32; }
    const float* zr = z + b * SDIM;
    const float* mr = mw.a[L] + (size_t)ci * SDIM;
    float s = 0.f;
#pragma unroll 4
    for (int k = lane; k < SDIM; k += 32) s += zr[k] * mr[k];
#pragma unroll
    for (int o = 16; o; o >>= 1) s += __shfl_xor_sync(0xffffffffu, s, o);
    if (lane == 0)
        style_ptr(L)[b * Ci + ci] = s * 0.04419417382415922f + mb.a[L][ci];
}

// ---------------- fused demod kernel, wsq inline ----------------
__global__ void demod_all_kernel(P5 w) {
    int gw = blockIdx.x * 8 + (threadIdx.x >> 5);
    int lane = threadIdx.x & 31;
    if (gw >= NB * 416) return;
    int b = gw / 416;
    int c = gw - b * 416;
    int L, co, Co, Ci;
    if (c < 128)      { L = 0; co = c;       Co = 128; Ci = 256; }
    else if (c < 256) { L = 1; co = c - 128; Co = 128; Ci = 128; }
    else if (c < 320) { L = 2; co = c - 256; Co = 64;  Ci = 128; }
    else if (c < 384) { L = 3; co = c - 320; Co = 64;  Ci = 64; }
    else              { L = 4; co = c - 384; Co = 32;  Ci = 64; }
    const float* st = style_ptr(L) + b * Ci;
    const float* wb = w.a[L] + (size_t)co * Ci * 9;
    float s = 0.f;
    for (int ci = lane; ci < Ci; ci += 32) {
        const float* p = wb + ci * 9;
        float wq = 0.f;
#pragma unroll
        for (int t = 0; t < 9; t++) wq += p[t] * p[t];
        float sv = st[ci];
        s += sv * sv * wq;
    }
#pragma unroll
    for (int o = 16; o; o >>= 1) s += __shfl_xor_sync(0xffffffffu, s, o);
    if (lane == 0)
        demod_ptr(L)[b * Co + co] = rsqrtf(s * (1.0f / (float)(Ci * 9)) + 1e-8f);
}

// ---------------- compose: bufA = (fg + (1-mask)*bg) * style0 ----------------
__global__ void compose_kernel(const float* __restrict__ fg,
                               const float* __restrict__ mask,
                               const float* __restrict__ bg) {
    int idx = blockIdx.x * blockDim.x + threadIdx.x;
    int p = idx & 1023;
    int c = (idx >> 10) & 255;
    int b = idx >> 18;
    float m = 1.0f - mask[b * 1024 + p];
    float v = fg[idx] + m * bg[idx];
    g_bufA[idx] = v * g_style0[b * 256 + c];
}

// ---------------- 3x3 conv, pad 1, f32x2; shift/mask staging; split-K -------
template <int CIN_TOT, int CIN_DO, int COUT, int H, int W, bool SRC_A, int CO_T,
          int NSPLIT>
__global__ __launch_bounds__(256) void conv3x3_kernel(const float* __restrict__ wraw,
                                                      const float* __restrict__ bias,
                                                      int demod_id, int style_id) {
    constexpr int CI_T = 8, TH = 8, TW = 32;
    constexpr int CO_PW = CO_T / 8;
    constexpr int JP = CO_PW / 2;
    constexpr int IN_LD = 36;
    constexpr int W_LD = CO_T + 2;
    constexpr int TILES_X = W / TW;
    __shared__ __align__(16) float s_in[TH + 2][CI_T + 1][IN_LD];
    __shared__ __align__(16) float s_w[CI_T][9][W_LD];

    const float* in = SRC_A ? g_bufA : g_bufB;
    float* out = SRC_A ? g_bufB : g_bufA;
    const float* demod = demod_ptr(demod_id);
    const float* styn = style_ptr(style_id);

    int tid = threadIdx.x;
    int tile = blockIdx.x;
    int tx0 = (tile % TILES_X) * TW;
    int ty0 = (tile / TILES_X) * TH;
    int co_base = blockIdx.y * CO_T;

    int b = blockIdx.z / NSPLIT;
    int half = blockIdx.z % NSPLIT;
    int cin_off = half * CIN_DO;

    int warp = tid >> 5;
    int lane = tid & 31;
    int r = lane >> 2;
    int c0 = (lane & 3) << 3;

    ull acc[JP][8];
#pragma unroll
    for (int jp = 0; jp < JP; jp++)
#pragma unroll
        for (int p = 0; p < 8; p++) acc[jp][p] = 0ull;

    const float wscale = rsqrtf((float)(CIN_TOT * 9));
    const float* in_b = in + (size_t)b * CIN_TOT * H * W;

    int colA = tid & 31;
    int gxA = tx0 + colA - 1;
    bool gxA_ok = (gxA >= 0 && gxA < W);
    int ixB = 32 + (tid & 1);
    int rowB = tid >> 1;
    int iyB = rowB >> 3, ciB = rowB & 7;
    int gxB = tx0 + ixB - 1;
    int gyB = ty0 + iyB - 1;
    bool B_ok = (tid < 160) && gxB >= 0 && gxB < W && gyB >= 0 && gyB < H;

    for (int cb = 0; cb < CIN_DO; cb += CI_T) {
        __syncthreads();
        const float* in_c = in_b + (size_t)(cin_off + cb) * H * W;
#pragma unroll
        for (int k = 0; k < 10; k++) {
            int rowq = (tid + k * 256) >> 5;
            int iy = rowq >> 3;
            int ci = rowq & 7;
            int gy = ty0 + iy - 1;
            float v = 0.f;
            if (gy >= 0 && gy < H && gxA_ok)
                v = in_c[ci * H * W + gy * W + gxA];
            s_in[iy][ci][colA] = v;
        }
        {
            float v = 0.f;
            if (B_ok) v = in_c[ciB * H * W + gyB * W + gxB];
            if (tid < 160) s_in[iyB][ciB][ixB] = v;
        }
#pragma unroll
        for (int k = 0; k < 9; k++) {
            int idx = tid + k * 256;
            int co = idx / (CI_T * 9);
            int rem = idx % (CI_T * 9);
            int ci = rem / 9, tap = rem % 9;
            s_w[ci][tap][co] =
                wraw[((size_t)(co_base + co) * CIN_TOT + cin_off + cb + ci) * 9 +
                     tap] * wscale;
        }
        __syncthreads();
#pragma unroll
        for (int ci = 0; ci < CI_T; ci++) {
#pragma unroll
            for (int ky = 0; ky < 3; ky++) {
                const float4* row4 =
                    reinterpret_cast<const float4*>(&s_in[r + ky][ci][c0]);
                float4 q0 = row4[0];
                float4 q1 = row4[1];
                float4 q2 = row4[2];
                ull xd[10];
                xd[0] = pack2(q0.x, q0.x); xd[1] = pack2(q0.y, q0.y);
                xd[2] = pack2(q0.z, q0.z); xd[3] = pack2(q0.w, q0.w);
                xd[4] = pack2(q1.x, q1.x); xd[5] = pack2(q1.y, q1.y);
                xd[6] = pack2(q1.z, q1.z); xd[7] = pack2(q1.w, q1.w);
                xd[8] = pack2(q2.x, q2.x); xd[9] = pack2(q2.y, q2.y);
#pragma unroll
                for (int kx = 0; kx < 3; kx++) {
#pragma unroll
                    for (int jp = 0; jp < JP; jp++) {
                        ull w2 = *reinterpret_cast<const ull*>(
                            &s_w[ci][ky * 3 + kx][warp * CO_PW + jp * 2]);
#pragma unroll
                        for (int p = 0; p < 8; p++) ffma2(acc[jp][p], w2, xd[kx + p]);
                    }
                }
            }
        }
    }
    int oy = ty0 + r;
#pragma unroll
    for (int jp = 0; jp < JP; jp++) {
        float vlo[8], vhi[8];
#pragma unroll
        for (int p = 0; p < 8; p++) unpack2(acc[jp][p], vlo[p], vhi[p]);
#pragma unroll
        for (int h = 0; h < 2; h++) {
            int co = co_base + warp * CO_PW + jp * 2 + h;
            const float* src = h ? vhi : vlo;
            if (NSPLIT > 1) {
                float* pp = g_part +
                            (((size_t)half * NB + b) * COUT + co) * H * W +
                            oy * W + tx0 + c0;
                float4 o0, o1;
                o0.x = src[0]; o0.y = src[1]; o0.z = src[2]; o0.w = src[3];
                o1.x = src[4]; o1.y = src[5]; o1.z = src[6]; o1.w = src[7];
                reinterpret_cast<float4*>(pp)[0] = o0;
                reinterpret_cast<float4*>(pp)[1] = o1;
            } else {
                float dm = demod[b * COUT + co];
                float bi = bias[co];
                float sn = styn[b * COUT + co];
                float* op = out + (size_t)b * COUT * H * W +
                            (size_t)co * H * W + oy * W + tx0 + c0;
                float4 o0, o1;
                float vv[8];
#pragma unroll
                for (int p = 0; p < 8; p++) {
                    float v = src[p] * dm + bi;
                    vv[p] = (v > 0.f ? v : 0.2f * v) * 1.41421356237309515f * sn;
                }
                o0.x = vv[0]; o0.y = vv[1]; o0.z = vv[2]; o0.w = vv[3];
                o1.x = vv[4]; o1.y = vv[5]; o1.z = vv[6]; o1.w = vv[7];
                reinterpret_cast<float4*>(op)[0] = o0;
                reinterpret_cast<float4*>(op)[1] = o1;
            }
        }
    }
}

// ---------------- split-K combine ----------------
template <int CO, int HW, int NHALF, bool DST_B>
__global__ void combine_kernel(const float* __restrict__ bias,
                               int demod_id, int style_id) {
    int idx = blockIdx.x * blockDim.x + threadIdx.x;
    constexpr int COHW = CO * HW;
    int b = idx / COHW;
    int co = (idx / HW) & (CO - 1);
    float p = 0.f;
#pragma unroll
    for (int h = 0; h < NHALF; h++) p += g_part[idx + (size_t)h * NB * COHW];
    float v = p * demod_ptr(demod_id)[b * CO + co] + bias[co];
    v = (v > 0.f ? v : 0.2f * v) * 1.41421356237309515f *
        style_ptr(style_id)[b * CO + co];
    (DST_B ? g_bufB : g_bufA)[idx] = v;
}

// ---------------- transposed conv: dense interior [0, 2*HIN)^2 --------------
// Grid covers exactly 2*HIN x 2*HIN; inner math identical to R11 winner.
template <int CIN, int COUT, int HIN, bool SRC_A>
__global__ __launch_bounds__(256) void tconv_kernel(const float* __restrict__ wraw,
                                                    int demod_id) {
    constexpr int HOUT = 2 * HIN + 1;
    constexpr int CO_T = 32, CI_T = 8, TH = 8, TW = 32;
    constexpr int IR = 6, ICW = 18, IC_LD = 19;
    constexpr int W_LD = 34;
    constexpr int TILES_X = (2 * HIN) / TW;   // dense interior only
    __shared__ __align__(16) float s_in[CI_T][IR][IC_LD];
    __shared__ __align__(16) float s_w[CI_T][9][W_LD];

    const float* in = SRC_A ? g_bufA : g_bufB;
    float* out = SRC_A ? g_bufB : g_bufA;
    const float* demod = demod_ptr(demod_id);

    int tid = threadIdx.x;
    int tile = blockIdx.x;
    int tx0 = (tile % TILES_X) * TW;
    int ty0 = (tile / TILES_X) * TH;
    int co_base = blockIdx.y * CO_T;
    int b = blockIdx.z;

    int co_grp = tid >> 6;
    int lane = tid & 31;
    int wrp = tid >> 5;
    int r = 2 * ((lane >> 3) & 3) + (wrp & 1);
    int c0 = (lane & 7) << 2;
    int h = c0 >> 1;

    int iy_base = (ty0 >> 1) - 1;
    int jx_base = (tx0 >> 1) - 1;

    ull acc[4][4];
#pragma unroll
    for (int jp = 0; jp < 4; jp++)
#pragma unroll
        for (int p = 0; p < 4; p++) acc[jp][p] = 0ull;

    const float wscale = rsqrtf((float)(CIN * 9));
    const float* in_b = in + (size_t)b * CIN * HIN * HIN;

    for (int cb = 0; cb < CIN; cb += CI_T) {
        __syncthreads();
        for (int idx = tid; idx < CI_T * IR * ICW; idx += 256) {
            int ci = idx / (IR * ICW);
            int rem = idx % (IR * ICW);
            int iy = rem / ICW, ix = rem % ICW;
            int gy = iy_base + iy, gx = jx_base + ix;
            float v = 0.f;
            if (gy >= 0 && gy < HIN && gx >= 0 && gx < HIN)
                v = in_b[(size_t)(cb + ci) * HIN * HIN + gy * HIN + gx];
            s_in[ci][iy][ix] = v;
        }
        for (int idx = tid; idx < CO_T * CI_T * 9; idx += 256) {
            int co = idx / (CI_T * 9);
            int rem = idx % (CI_T * 9);
            int ci = rem / 9, tap = rem % 9;
            s_w[ci][tap][co] =
                wraw[((size_t)(co_base + co) * CIN + cb + ci) * 9 + tap] * wscale;
        }
        __syncthreads();
#pragma unroll
        for (int ci = 0; ci < CI_T; ci++) {
            int ky0 = r & 1;
            for (int ky = ky0; ky < 3; ky += 2) {
                int ir = ((r + ky - 2) >> 1) + 1;
                float x0v = s_in[ci][ir][h];
                float x1v = s_in[ci][ir][h + 1];
                float x2v = s_in[ci][ir][h + 2];
                ull xd0 = pack2(x0v, x0v);
                ull xd1 = pack2(x1v, x1v);
                ull xd2 = pack2(x2v, x2v);
                int wr = (2 - ky) * 3;
#pragma unroll
                for (int jp = 0; jp < 4; jp++) {
                    int co = co_grp * 8 + jp * 2;
                    ull w0 = *reinterpret_cast<const ull*>(&s_w[ci][wr + 0][co]);
                    ull w1 = *reinterpret_cast<const ull*>(&s_w[ci][wr + 1][co]);
                    ull w2 = *reinterpret_cast<const ull*>(&s_w[ci][wr + 2][co]);
                    ffma2(acc[jp][0], w2, xd0);
                    ffma2(acc[jp][0], w0, xd1);
                    ffma2(acc[jp][1], w1, xd1);
                    ffma2(acc[jp][2], w2, xd1);
                    ffma2(acc[jp][2], w0, xd2);
                    ffma2(acc[jp][3], w1, xd2);
                }
            }
        }
    }
    int oy = ty0 + r;   // < 2*HIN by construction
    float* out_b = out + (size_t)b * COUT * HOUT * HOUT;
#pragma unroll
    for (int jp = 0; jp < 4; jp++) {
#pragma unroll
        for (int hh = 0; hh < 2; hh++) {
            int co = co_base + co_grp * 8 + jp * 2 + hh;
            float dm = demod[b * COUT + co];
#pragma unroll
            for (int p = 0; p < 4; p++) {
                float lo, hi;
                unpack2(acc[jp][p], lo, hi);
                out_b[(size_t)co * HOUT * HOUT + oy * HOUT + tx0 + c0 + p] =
                    (hh ? hi : lo) * dm;
            }
        }
    }
}

// ---------------- tconv edge strips: last column (s=0) / last row (s=1) -----
// out col 2*HIN uses only input col HIN-1; out row 2*HIN only input row HIN-1.
// 1-D conv over smem-staged line + 3-tap weight vectors.
template <int CIN, int COUT, int HIN, bool SRC_A>
__global__ __launch_bounds__(256) void tconv_edge_kernel(
    const float* __restrict__ wraw, int demod_id) {
    constexpr int HOUT = 2 * HIN + 1;
    __shared__ float s_line[CIN][HIN];
    __shared__ float s_w3[CIN][3][33];

    const float* in = SRC_A ? g_bufA : g_bufB;
    float* out = SRC_A ? g_bufB : g_bufA;

    int s = blockIdx.y;            // 0: col strip, 1: row strip (excl corner)
    int co_base = blockIdx.x * 32;
    int b = blockIdx.z;
    int tid = threadIdx.x;
    const float* in_b = in + (size_t)b * CIN * HIN * HIN;

    for (int e = tid; e < CIN * HIN; e += 256) {
        int ci = e / HIN, t = e % HIN;   // HIN pow2 -> shifts
        s_line[ci][t] = (s == 0)
            ? in_b[(size_t)ci * HIN * HIN + t * HIN + (HIN - 1)]
            : in_b[(size_t)ci * HIN * HIN + (HIN - 1) * HIN + t];
    }
    const float wscale = rsqrtf((float)(CIN * 9));
    for (int e = tid; e < 32 * CIN * 3; e += 256) {
        int co = e / (CIN * 3);
        int rem = e % (CIN * 3);
        int ci = rem / 3, k = rem % 3;
        int widx = (s == 0) ? ((2 - k) * 3 + 2) : (2 * 3 + (2 - k));
        s_w3[ci][k][co] =
            wraw[((size_t)(co_base + co) * CIN + ci) * 9 + widx] * wscale;
    }
    __syncthreads();

    int co = tid & 31;
    float dm = demod_ptr(demod_id)[b * COUT + co_base + co];
    float* out_b = out + ((size_t)b * COUT + co_base + co) * HOUT * HOUT;
    int nmax = HOUT - s;   // s=1 excludes the corner (owned by s=0)
    for (int n = tid >> 5; n < nmax; n += 8) {
        float acc = 0.f;
        if (n & 1) {
            int iy = (n - 1) >> 1;
#pragma unroll 4
            for (int ci = 0; ci < CIN; ci++)
                acc += s_line[ci][iy] * s_w3[ci][1][co];
        } else {
            int hh = n >> 1;
            if (hh >= 1) {
#pragma unroll 4
                for (int ci = 0; ci < CIN; ci++)
                    acc += s_line[ci][hh - 1] * s_w3[ci][0][co];
            }
            if (hh < HIN) {
#pragma unroll 4
                for (int ci = 0; ci < CIN; ci++)
                    acc += s_line[ci][hh] * s_w3[ci][2][co];
            }
        }
        acc *= dm;
        if (s == 0) out_b[n * HOUT + (HOUT - 1)] = acc;
        else out_b[(HOUT - 1) * HOUT + n] = acc;
    }
}

// ---------------- 4x4 blur + bias + leaky*sqrt2*style_next ----------------
template <int C, int HIN, bool SRC_A>
__global__ __launch_bounds__(256) void blur_kernel(const float* __restrict__ bias,
                                                   int style_id) {
    constexpr int HOUT = HIN - 1;
    constexpr int TH = 16, TW = 32;
    constexpr int TILES_X = HOUT / TW;
    __shared__ float s[TH + 3][TW + 4];

    const float* in = SRC_A ? g_bufA : g_bufB;
    float* out = SRC_A ? g_bufB : g_bufA;

    int tile = blockIdx.x;
    int x0 = (tile % TILES_X) * TW;
    int y0 = (tile / TILES_X) * TH;
    int c = blockIdx.y, b = blockIdx.z;
    const float* ip = in + ((size_t)b * C + c) * HIN * HIN;

    for (int idx = threadIdx.x; idx < (TH + 3) * (TW + 3); idx += 256) {
        int iy = idx / (TW + 3), ix = idx % (TW + 3);
        int gy = y0 + iy - 1, gx = x0 + ix - 1;
        float v = 0.f;
        if (gy >= 0 && gy < HIN && gx >= 0 && gx < HIN) v = ip[gy * HIN + gx];
        s[iy][ix] = v;
    }
    __syncthreads();

    const float c4[4] = {0.25f, 0.75f, 0.75f, 0.25f};
    float bi = bias[c];
    float sn = style_ptr(style_id)[b * C + c];
    float* op = out + ((size_t)b * C + c) * HOUT * HOUT;
#pragma unroll
    for (int q = 0; q < 2; q++) {
        int px = threadIdx.x + q * 256;
        int ly = px >> 5, lx = px & 31;
        float a = 0.f;
#pragma unroll
        for (int ky = 0; ky < 4; ky++) {
            float rs = 0.f;
#pragma unroll
            for (int kx = 0; kx < 4; kx++) rs += c4[kx] * s[ly + ky][lx + kx];
            a += c4[ky] * rs;
        }
        a += bi;
        a = (a > 0.f ? a : 0.2f * a) * 1.41421356237309515f * sn;
        op[(y0 + ly) * HOUT + x0 + lx] = a;
    }
}

// ---------------- final 1x1 (32 -> 3 of 4 ch), + out_bias ----------------
__global__ void final_kernel(const float* __restrict__ finw,
                             const float* __restrict__ outb,
                             float* __restrict__ out) {
    int idx = blockIdx.x * blockDim.x + threadIdx.x;
    int b = idx >> 14;
    int p = idx & 16383;
    const float* ib = g_bufB + (size_t)b * 32 * 16384 + p;
    float a0 = 0.f, a1 = 0.f, a2 = 0.f;
#pragma unroll
    for (int ci = 0; ci < 32; ci++) {
        float v = ib[(size_t)ci * 16384];
        a0 = fmaf(finw[ci], v, a0);
        a1 = fmaf(finw[32 + ci], v, a1);
        a2 = fmaf(finw[64 + ci], v, a2);
    }
    const float sc = rsqrtf(32.0f);
    out[(size_t)b * 3 * 16384 + p] = a0 * sc + outb[0];
    out[(size_t)b * 3 * 16384 + 16384 + p] = a1 * sc + outb[1];
    out[(size_t)b * 3 * 16384 + 2 * 16384 + p] = a2 * sc + outb[2];
}

// ------------------------------------------------------------------------
extern "C" void kernel_launch(void* const* d_in, const int* in_sizes, int n_in,
                              void* d_out, int out_size) {
    (void)in_sizes; (void)n_in; (void)out_size;
    const float* fg = (const float*)d_in[0];
    const float* mask = (const float*)d_in[1];
    const float* bg = (const float*)d_in[2];
    const float* z = (const float*)d_in[3];
    const float* l_w[5]  = {(const float*)d_in[4],  (const float*)d_in[8],
                            (const float*)d_in[12], (const float*)d_in[16],
                            (const float*)d_in[20]};
    const float* l_mw[5] = {(const float*)d_in[5],  (const float*)d_in[9],
                            (const float*)d_in[13], (const float*)d_in[17],
                            (const float*)d_in[21]};
    const float* l_mb[5] = {(const float*)d_in[6],  (const float*)d_in[10],
                            (const float*)d_in[14], (const float*)d_in[18],
                            (const float*)d_in[22]};
    const float* l_b[5]  = {(const float*)d_in[7],  (const float*)d_in[11],
                            (const float*)d_in[15], (const float*)d_in[19],
                            (const float*)d_in[23]};
    const float* finw = (const float*)d_in[24];
    const float* fin_mw = (const float*)d_in[25];
    const float* fin_mb = (const float*)d_in[26];
    const float* outb = (const float*)d_in[27];

    // fused setup: 2 kernels
    P6 mw6, mb6;
    for (int l = 0; l < 5; l++) { mw6.a[l] = l_mw[l]; mb6.a[l] = l_mb[l]; }
    mw6.a[5] = fin_mw; mb6.a[5] = fin_mb;
    style_all_kernel<<<1344, 256>>>(z, mw6, mb6);
    P5 w5;
    for (int l = 0; l < 5; l++) w5.a[l] = l_w[l];
    demod_all_kernel<<<832, 256>>>(w5);

    // compose + modulate for layer 0 -> bufA
    compose_kernel<<<(NB * 256 * 1024) / 256, 256>>>(fg, mask, bg);

    // l0: 256->128 @32x32, split-K=4 -> 1024 CTAs
    conv3x3_kernel<256, 64, 128, 32, 32, true, 32, 4>
        <<<dim3(4, 4, 64), 256>>>(l_w[0], l_b[0], 0, 1);
    combine_kernel<128, 1024, 4, true><<<8192, 256>>>(l_b[0], 0, 1);
    // l1: tconv 128->128, 32 -> 65 (B -> A): dense 64x64 interior + edges
    tconv_kernel<128, 128, 32, false><<<dim3(16, 4, NB), 256>>>(l_w[1], 1);
    tconv_edge_kernel<128, 128, 32, false><<<dim3(4, 2, NB), 256>>>(l_w[1], 1);
    // blur 65 -> 64 + act + style2   (A -> B)
    blur_kernel<128, 65, true><<<dim3(8, 128, NB), 256>>>(l_b[1], 2);
    // l2: 128->64 @64x64, split-K=2 -> 1024 CTAs
    conv3x3_kernel<128, 64, 64, 64, 64, false, 32, 2>
        <<<dim3(16, 2, 32), 256>>>(l_w[2], l_b[2], 2, 3);
    combine_kernel<64, 4096, 2, false><<<16384, 256>>>(l_b[2], 2, 3);
    // l3: tconv 64->64, 64 -> 129 (A -> B): dense 128x128 interior + edges
    tconv_kernel<64, 64, 64, true><<<dim3(64, 2, NB), 256>>>(l_w[3], 3);
    tconv_edge_kernel<64, 64, 64, true><<<dim3(2, 2, NB), 256>>>(l_w[3], 3);
    // blur 129 -> 128 + act + style4   (B -> A)
    blur_kernel<64, 129, false><<<dim3(32, 64, NB), 256>>>(l_b[3], 4);
    // l4: 64->32 @128x128   (A -> B)
    conv3x3_kernel<64, 64, 32, 128, 128, true, 32, 1>
        <<<dim3(64, 1, 16), 256>>>(l_w[4], l_b[4], 4, 5);
    // final 1x1 32->3 + out_bias   (B -> d_out)
    final_kernel<<<(NB * 16384) / 256, 256>>>(finw, outb, (float*)d_out);
}